// round 7
// baseline (speedup 1.0000x reference)
#include <cuda_runtime.h>
#include <cuda_bf16.h>
#include <cstdint>

// Problem constants
#define BDIM   1024
#define BRANK  64
#define BHEADS 16
#define BB     2
#define BT     2048

#define SPLITK 4
#define OUTSZ  ((size_t)BB * BT * BDIM)   // 4194304

// ---------------------------------------------------------------------------
// Scratch (device globals)
// ---------------------------------------------------------------------------
__device__ __align__(256) __nv_bfloat16 g_phi[(size_t)BB * BHEADS * BT * BT];
__device__ __align__(256) __nv_bfloat16 g_plo[(size_t)BB * BHEADS * BT * BT];
__device__ __align__(256) float g_part[(size_t)BB * BHEADS * BT * 16];
__device__ __align__(256) float g_rinv[(size_t)BB * BHEADS * BT];
__device__ __align__(256) float g_out4[SPLITK * OUTSZ];                 // split-K partials
__device__ __align__(256) __nv_bfloat16 g_xhi[(size_t)BB * BT * BDIM];
__device__ __align__(256) __nv_bfloat16 g_xlo[(size_t)BB * BT * BDIM];
__device__ __align__(256) __nv_bfloat16 g_qkhi[(size_t)2 * BHEADS * BRANK * BDIM];
__device__ __align__(256) __nv_bfloat16 g_qklo[(size_t)2 * BHEADS * BRANK * BDIM];
__device__ __align__(256) __nv_bfloat16 g_xqhi[(size_t)BB * BT * BHEADS * BRANK];
__device__ __align__(256) __nv_bfloat16 g_xqlo[(size_t)BB * BT * BHEADS * BRANK];
__device__ __align__(256) __nv_bfloat16 g_xkhi[(size_t)BB * BT * BHEADS * BRANK];
__device__ __align__(256) __nv_bfloat16 g_xklo[(size_t)BB * BT * BHEADS * BRANK];
__device__ __align__(256) __nv_bfloat16 g_xthi[(size_t)BB * BDIM * BT];
__device__ __align__(256) __nv_bfloat16 g_xtlo[(size_t)BB * BDIM * BT];
__device__ __align__(256) __nv_bfloat16 g_ctxhi[(size_t)BB * BT * BHEADS * BDIM];
__device__ __align__(256) __nv_bfloat16 g_ctxlo[(size_t)BB * BT * BHEADS * BDIM];
__device__ __align__(256) __nv_bfloat16 g_vothi[(size_t)BDIM * BHEADS * BDIM];
__device__ __align__(256) __nv_bfloat16 g_votlo[(size_t)BDIM * BHEADS * BDIM];

// ---------------------------------------------------------------------------
// Helpers
// ---------------------------------------------------------------------------
__device__ __forceinline__ uint32_t smem_u32(const void* p) {
    return (uint32_t)__cvta_generic_to_shared(p);
}

#define CP16(s, g) asm volatile("cp.async.cg.shared.global [%0], [%1], 16;" :: "r"(s), "l"(g))

__device__ __forceinline__ void ldsm4(uint32_t* r, uint32_t addr) {
    asm volatile("ldmatrix.sync.aligned.m8n8.x4.shared.b16 {%0,%1,%2,%3}, [%4];"
        : "=r"(r[0]), "=r"(r[1]), "=r"(r[2]), "=r"(r[3]) : "r"(addr));
}

__device__ __forceinline__ void mma16816(float* c, const uint32_t* a, const uint32_t* b) {
    asm volatile("mma.sync.aligned.m16n8k16.row.col.f32.bf16.bf16.f32 "
        "{%0,%1,%2,%3}, {%4,%5,%6,%7}, {%8,%9}, {%0,%1,%2,%3};"
        : "+f"(c[0]), "+f"(c[1]), "+f"(c[2]), "+f"(c[3])
        : "r"(a[0]), "r"(a[1]), "r"(a[2]), "r"(a[3]), "r"(b[0]), "r"(b[1]));
}

template <int N>
__device__ __forceinline__ void cp_wait() {
    asm volatile("cp.async.wait_group %0;" :: "n"(N) : "memory");
}

// ---------------------------------------------------------------------------
// Elementwise hi/lo split
// ---------------------------------------------------------------------------
__global__ __launch_bounds__(256)
void split_f32(const float* __restrict__ in,
               __nv_bfloat16* __restrict__ oh, __nv_bfloat16* __restrict__ ol,
               long long n4)
{
    const long long i = (long long)blockIdx.x * 256 + threadIdx.x;
    if (i >= n4) return;
    float4 v = reinterpret_cast<const float4*>(in)[i];
    __nv_bfloat162 h01, h23, l01, l23;
    h01.x = __float2bfloat16(v.x); h01.y = __float2bfloat16(v.y);
    h23.x = __float2bfloat16(v.z); h23.y = __float2bfloat16(v.w);
    l01.x = __float2bfloat16(v.x - __bfloat162float(h01.x));
    l01.y = __float2bfloat16(v.y - __bfloat162float(h01.y));
    l23.x = __float2bfloat16(v.z - __bfloat162float(h23.x));
    l23.y = __float2bfloat16(v.w - __bfloat162float(h23.y));
    reinterpret_cast<__nv_bfloat162*>(oh)[2 * i + 0] = h01;
    reinterpret_cast<__nv_bfloat162*>(oh)[2 * i + 1] = h23;
    reinterpret_cast<__nv_bfloat162*>(ol)[2 * i + 0] = l01;
    reinterpret_cast<__nv_bfloat162*>(ol)[2 * i + 1] = l23;
}

// ---------------------------------------------------------------------------
// Transpose + hi/lo split, vectorized bf16x2 stores. 32x32 tiles, 256 thr.
// out[c][r] = in[r][c]
// ---------------------------------------------------------------------------
__global__ __launch_bounds__(256)
void transpose_split(const float* __restrict__ in, long long inBS, int R, int C,
                     __nv_bfloat16* __restrict__ oh, __nv_bfloat16* __restrict__ ol,
                     int oLd, long long oBS)
{
    __shared__ float tile[32][34];
    const int z = blockIdx.z;
    const float* ip = in + (long long)z * inBS;
    const int c0 = blockIdx.x * 32;
    const int r0 = blockIdx.y * 32;
    const int t  = threadIdx.x;
    const int tx = t & 31;
    const int ty = t >> 5;

#pragma unroll
    for (int i = 0; i < 4; i++)
        tile[ty + 8 * i][tx] = ip[(long long)(r0 + ty + 8 * i) * C + c0 + tx];
    __syncthreads();

    const long long ob = (long long)z * oBS;
    const int c = t >> 3;          // 0..31
#pragma unroll
    for (int it = 0; it < 2; it++) {
        const int rp = (t & 7) + 8 * it;   // 0..15 -> rows 2rp, 2rp+1
        const float v0 = tile[2 * rp + 0][c];
        const float v1 = tile[2 * rp + 1][c];
        __nv_bfloat162 hv, lv;
        hv.x = __float2bfloat16(v0);
        hv.y = __float2bfloat16(v1);
        lv.x = __float2bfloat16(v0 - __bfloat162float(hv.x));
        lv.y = __float2bfloat16(v1 - __bfloat162float(hv.y));
        const long long o = ob + (long long)(c0 + c) * oLd + r0 + 2 * rp;
        *reinterpret_cast<__nv_bfloat162*>(oh + o) = hv;
        *reinterpret_cast<__nv_bfloat162*>(ol + o) = lv;
    }
}

// ---------------------------------------------------------------------------
// Reduce 16 per-row partials -> 1/rowsum
// ---------------------------------------------------------------------------
__global__ __launch_bounds__(256)
void reduce_inv(const float* __restrict__ part, float* __restrict__ inv)
{
    const long long r = (long long)blockIdx.x * 256 + threadIdx.x;
    const float4* p = reinterpret_cast<const float4*>(part + r * 16);
    float4 a = p[0], b = p[1], c = p[2], d = p[3];
    float s = ((a.x + a.y) + (a.z + a.w)) + ((b.x + b.y) + (b.z + b.w))
            + ((c.x + c.y) + (c.z + c.w)) + ((d.x + d.y) + (d.z + d.w));
    inv[r] = 1.0f / s;
}

// ---------------------------------------------------------------------------
// Sum 4 split-K partials -> out (deterministic order)
// ---------------------------------------------------------------------------
__global__ __launch_bounds__(256)
void add4(const float* __restrict__ p, float* __restrict__ out)
{
    const long long i = (long long)blockIdx.x * 256 + threadIdx.x;
    const float4 a = reinterpret_cast<const float4*>(p)[i];
    const float4 b = reinterpret_cast<const float4*>(p + OUTSZ)[i];
    const float4 c = reinterpret_cast<const float4*>(p + 2 * OUTSZ)[i];
    const float4 d = reinterpret_cast<const float4*>(p + 3 * OUTSZ)[i];
    float4 r;
    r.x = (a.x + b.x) + (c.x + d.x);
    r.y = (a.y + b.y) + (c.y + d.y);
    r.z = (a.z + b.z) + (c.z + d.z);
    r.w = (a.w + b.w) + (c.w + d.w);
    reinterpret_cast<float4*>(out)[i] = r;
}

// ---------------------------------------------------------------------------
// HMMA bf16-split GEMM, 3-stage cp.async pipeline, 128x128 tile, KC=64.
// STAGE==1: epilogue hi/lo split; ncol<1024 -> (Chi,Clo)=xq else (Chi2,Clo2)=xk.
// STAGE==3: z=(b,h); epilogue exp hi/lo -> E + deterministic partial row sums.
// STAGE==4: A=E flat; B=xT per batch; epilogue *= Rinv, ctx hi/lo scatter.
// STAGE==5: split-K over blockIdx.z; fp32 partial per z.
// ---------------------------------------------------------------------------
#define HTM 128
#define HTN 128
#define HTK 64

#define BUFSTRIDE 65536
#define AHI_O 0
#define ALO_O 16384
#define BHI_O 32768
#define BLO_O 49152
#define HMMA_SMEM (3 * BUFSTRIDE)   // 192 KB

template <int STAGE>
__global__ __launch_bounds__(256, (STAGE == 3) ? 2 : 1)
void hmma_gemm(const __nv_bfloat16* __restrict__ Ahi, const __nv_bfloat16* __restrict__ Alo,
               int lda,
               const __nv_bfloat16* __restrict__ Bhi, const __nv_bfloat16* __restrict__ Blo,
               int ldb,
               float* __restrict__ Cf,
               __nv_bfloat16* __restrict__ Chi, __nv_bfloat16* __restrict__ Clo,
               __nv_bfloat16* __restrict__ Chi2, __nv_bfloat16* __restrict__ Clo2,
               const float* __restrict__ Rinv,
               int ldc, int K, float alpha)
{
    extern __shared__ char smem[];
    __shared__ float srow[2][HTM];
    const uint32_t sb = smem_u32(smem);
    const int tid  = threadIdx.x;
    const int wid  = tid >> 5;
    const int lane = tid & 31;
    const int mw = wid & 3;
    const int nw = wid >> 2;

    const long long m0 = (long long)blockIdx.y * HTM;
    const int n0 = blockIdx.x * HTN;

    const __nv_bfloat16 *Abh, *Abl, *Bbh, *Bbl;
    if (STAGE == 3) {
        const int z = blockIdx.z;
        const int b = z >> 4;
        const int h = z & 15;
        const long long ao = ((long long)b * BT + m0) * lda + h * BRANK;
        const long long bo = ((long long)b * BT + n0) * ldb + h * BRANK;
        Abh = Ahi + ao;  Abl = Alo + ao;
        Bbh = Bhi + bo;  Bbl = Blo + bo;
    } else if (STAGE == 4) {
        const long long b = m0 >> 15;
        Abh = Ahi + m0 * lda;  Abl = Alo + m0 * lda;
        const long long bo = b * ((long long)BDIM * BT) + (long long)n0 * ldb;
        Bbh = Bhi + bo;  Bbl = Blo + bo;
    } else if (STAGE == 5) {
        const long long koff = (long long)blockIdx.z * K;   // K = per-split K
        Abh = Ahi + m0 * lda + koff;  Abl = Alo + m0 * lda + koff;
        Bbh = Bhi + (long long)n0 * ldb + koff;
        Bbl = Blo + (long long)n0 * ldb + koff;
    } else {
        Abh = Ahi + m0 * lda;  Abl = Alo + m0 * lda;
        Bbh = Bhi + (long long)n0 * ldb;  Bbl = Blo + (long long)n0 * ldb;
    }

    float acc[2][8][4];
#pragma unroll
    for (int i = 0; i < 2; i++)
#pragma unroll
        for (int f = 0; f < 8; f++)
#pragma unroll
            for (int e = 0; e < 4; e++) acc[i][f][e] = 0.0f;

    const int NC = K / HTK;

    auto load_chunk = [&](int c, int buf) {
        const long long kg = (long long)c * HTK;
        const uint32_t bb = sb + buf * BUFSTRIDE;
#pragma unroll
        for (int i = 0; i < 4; i++) {
            const int idx = tid + i * 256;
            const int r  = idx >> 3;
            const int ck = idx & 7;
            const uint32_t so = (uint32_t)(r * 128 + ((ck ^ (r & 7)) << 4));
            const long long ga = (long long)r * lda + kg + ck * 8;
            const long long gb = (long long)r * ldb + kg + ck * 8;
            CP16(bb + AHI_O + so, (const void*)(Abh + ga));
            CP16(bb + ALO_O + so, (const void*)(Abl + ga));
            CP16(bb + BHI_O + so, (const void*)(Bbh + gb));
            CP16(bb + BLO_O + so, (const void*)(Bbl + gb));
        }
        asm volatile("cp.async.commit_group;" ::: "memory");
    };

    load_chunk(0, 0);
    if (NC > 1) load_chunk(1, 1);

    for (int c = 0; c < NC; c++) {
        if (c + 2 < NC) load_chunk(c + 2, (c + 2) % 3);
        const int pend = (NC - 1 - c >= 2) ? 2 : (NC - 1 - c);
        if (pend == 2)      cp_wait<2>();
        else if (pend == 1) cp_wait<1>();
        else                cp_wait<0>();
        __syncthreads();

        const uint32_t ab = sb + (c % 3) * BUFSTRIDE;
#pragma unroll
        for (int ks = 0; ks < 4; ks++) {
            uint32_t ah[2][4], al[2][4], bh[4][4], bl[4][4];
#pragma unroll
            for (int i = 0; i < 2; i++) {
                const int r  = mw * 32 + i * 16 + (lane & 15);
                const int ck = ks * 2 + (lane >> 4);
                const uint32_t off = (uint32_t)(r * 128 + ((ck ^ (r & 7)) << 4));
                ldsm4(ah[i], ab + AHI_O + off);
                ldsm4(al[i], ab + ALO_O + off);
            }
#pragma unroll
            for (int j = 0; j < 4; j++) {
                const int r  = nw * 64 + j * 16 + (lane & 7) + ((lane >> 4) & 1) * 8;
                const int ck = ks * 2 + ((lane >> 3) & 1);
                const uint32_t off = (uint32_t)(r * 128 + ((ck ^ (r & 7)) << 4));
                ldsm4(bh[j], ab + BHI_O + off);
                ldsm4(bl[j], ab + BLO_O + off);
            }
#pragma unroll
            for (int i = 0; i < 2; i++)
#pragma unroll
                for (int f = 0; f < 8; f++) {
                    const uint32_t* Bh = &bh[f >> 1][(f & 1) * 2];
                    const uint32_t* Bl = &bl[f >> 1][(f & 1) * 2];
                    mma16816(acc[i][f], ah[i], Bh);
                    mma16816(acc[i][f], ah[i], Bl);
                    mma16816(acc[i][f], al[i], Bh);
                }
        }
        __syncthreads();
    }

    // Epilogue
#pragma unroll
    for (int i = 0; i < 2; i++) {
#pragma unroll
        for (int hr = 0; hr < 2; hr++) {
            const long long mg = m0 + mw * 32 + i * 16 + hr * 8 + (lane >> 2);
            const int ncol = n0 + nw * 64 + (lane & 3) * 2;
            if (STAGE == 5) {
                float* dst = Cf + (long long)blockIdx.z * (long long)OUTSZ
                                + mg * ldc + ncol;
#pragma unroll
                for (int f = 0; f < 8; f++) {
                    float2 v;
                    v.x = acc[i][f][hr * 2 + 0];
                    v.y = acc[i][f][hr * 2 + 1];
                    *reinterpret_cast<float2*>(dst + f * 8) = v;
                }
            } else if (STAGE == 3) {
                const long long orow = (long long)blockIdx.z * BT * BT + mg * ldc + ncol;
                float part = 0.0f;
#pragma unroll
                for (int f = 0; f < 8; f++) {
                    const float e0 = __expf(acc[i][f][hr * 2 + 0] * alpha);
                    const float e1 = __expf(acc[i][f][hr * 2 + 1] * alpha);
                    part += e0 + e1;
                    __nv_bfloat162 hv, lv;
                    hv.x = __float2bfloat16(e0);
                    hv.y = __float2bfloat16(e1);
                    lv.x = __float2bfloat16(e0 - __bfloat162float(hv.x));
                    lv.y = __float2bfloat16(e1 - __bfloat162float(hv.y));
                    *reinterpret_cast<__nv_bfloat162*>(Chi + orow + f * 8) = hv;
                    *reinterpret_cast<__nv_bfloat162*>(Clo + orow + f * 8) = lv;
                }
                part += __shfl_xor_sync(0xffffffffu, part, 1);
                part += __shfl_xor_sync(0xffffffffu, part, 2);
                if ((lane & 3) == 0)
                    srow[nw][mw * 32 + i * 16 + hr * 8 + (lane >> 2)] = part;
            } else if (STAGE == 1) {
                const bool isK = (ncol >= 1024);
                __nv_bfloat16* DH = isK ? Chi2 : Chi;
                __nv_bfloat16* DL = isK ? Clo2 : Clo;
                const long long orow = mg * ldc + (ncol - (isK ? 1024 : 0));
#pragma unroll
                for (int f = 0; f < 8; f++) {
                    const float v0 = acc[i][f][hr * 2 + 0];
                    const float v1 = acc[i][f][hr * 2 + 1];
                    __nv_bfloat162 hv, lv;
                    hv.x = __float2bfloat16(v0);
                    hv.y = __float2bfloat16(v1);
                    lv.x = __float2bfloat16(v0 - __bfloat162float(hv.x));
                    lv.y = __float2bfloat16(v1 - __bfloat162float(hv.y));
                    *reinterpret_cast<__nv_bfloat162*>(DH + orow + f * 8) = hv;
                    *reinterpret_cast<__nv_bfloat162*>(DL + orow + f * 8) = lv;
                }
            } else { // STAGE == 4
                const float rs = Rinv[mg];
                const int b = (int)(mg >> 15);
                const int h = (int)((mg >> 11) & 15);
                const int t = (int)(mg & 2047);
                const long long orow =
                    ((long long)b * BT + t) * ((long long)BHEADS * BDIM) +
                    (long long)h * BDIM + ncol;
#pragma unroll
                for (int f = 0; f < 8; f++) {
                    const float v0 = acc[i][f][hr * 2 + 0] * rs;
                    const float v1 = acc[i][f][hr * 2 + 1] * rs;
                    __nv_bfloat162 hv, lv;
                    hv.x = __float2bfloat16(v0);
                    hv.y = __float2bfloat16(v1);
                    lv.x = __float2bfloat16(v0 - __bfloat162float(hv.x));
                    lv.y = __float2bfloat16(v1 - __bfloat162float(hv.y));
                    *reinterpret_cast<__nv_bfloat162*>(Chi + orow + f * 8) = hv;
                    *reinterpret_cast<__nv_bfloat162*>(Clo + orow + f * 8) = lv;
                }
            }
        }
    }

    if (STAGE == 3) {
        __syncthreads();
        if (tid < HTM) {
            const float s = srow[0][tid] + srow[1][tid];
            Cf[((long long)blockIdx.z * BT + m0 + tid) * 16 + blockIdx.x] = s;
        }
    }
}

// ---------------------------------------------------------------------------
// Launch
// ---------------------------------------------------------------------------
extern "C" void kernel_launch(void* const* d_in, const int* in_sizes, int n_in,
                              void* d_out, int out_size)
{
    const float* x  = (const float*)d_in[0];
    const float* Q  = (const float*)d_in[1];
    const float* K  = (const float*)d_in[2];
    const float* VO = (const float*)d_in[3];
    float* out = (float*)d_out;

    float *part, *rinv, *out4;
    __nv_bfloat16 *phi, *plo, *xhi, *xlo, *qkhi, *qklo;
    __nv_bfloat16 *xqhi, *xqlo, *xkhi, *xklo;
    __nv_bfloat16 *xthi, *xtlo, *ctxhi, *ctxlo, *vothi, *votlo;
    cudaGetSymbolAddress((void**)&part,  g_part);
    cudaGetSymbolAddress((void**)&rinv,  g_rinv);
    cudaGetSymbolAddress((void**)&out4,  g_out4);
    cudaGetSymbolAddress((void**)&phi,   g_phi);
    cudaGetSymbolAddress((void**)&plo,   g_plo);
    cudaGetSymbolAddress((void**)&xhi,   g_xhi);
    cudaGetSymbolAddress((void**)&xlo,   g_xlo);
    cudaGetSymbolAddress((void**)&qkhi,  g_qkhi);
    cudaGetSymbolAddress((void**)&qklo,  g_qklo);
    cudaGetSymbolAddress((void**)&xqhi,  g_xqhi);
    cudaGetSymbolAddress((void**)&xqlo,  g_xqlo);
    cudaGetSymbolAddress((void**)&xkhi,  g_xkhi);
    cudaGetSymbolAddress((void**)&xklo,  g_xklo);
    cudaGetSymbolAddress((void**)&xthi,  g_xthi);
    cudaGetSymbolAddress((void**)&xtlo,  g_xtlo);
    cudaGetSymbolAddress((void**)&ctxhi, g_ctxhi);
    cudaGetSymbolAddress((void**)&ctxlo, g_ctxlo);
    cudaGetSymbolAddress((void**)&vothi, g_vothi);
    cudaGetSymbolAddress((void**)&votlo, g_votlo);

    cudaFuncSetAttribute(hmma_gemm<1>, cudaFuncAttributeMaxDynamicSharedMemorySize, HMMA_SMEM);
    cudaFuncSetAttribute(hmma_gemm<3>, cudaFuncAttributeMaxDynamicSharedMemorySize, HMMA_SMEM);
    cudaFuncSetAttribute(hmma_gemm<4>, cudaFuncAttributeMaxDynamicSharedMemorySize, HMMA_SMEM);
    cudaFuncSetAttribute(hmma_gemm<5>, cudaFuncAttributeMaxDynamicSharedMemorySize, HMMA_SMEM);

    const int MBT = BB * BT;                  // 4096
    const int HR  = BHEADS * BRANK;           // 1024
    const int HD  = BHEADS * BDIM;            // 16384

    // Input splits
    split_f32<<<(MBT * BDIM / 4 + 255) / 256, 256>>>(x, xhi, xlo, (long long)MBT * BDIM / 4);
    split_f32<<<(HR * BDIM / 4 + 255) / 256, 256>>>(Q, qkhi, qklo, (long long)HR * BDIM / 4);
    split_f32<<<(HR * BDIM / 4 + 255) / 256, 256>>>(K, qkhi + (size_t)HR * BDIM,
                                                    qklo + (size_t)HR * BDIM,
                                                    (long long)HR * BDIM / 4);
    transpose_split<<<dim3(BDIM / 32, BT / 32, BB), 256>>>(
        x, (long long)BT * BDIM, BT, BDIM, xthi, xtlo, BT, (long long)BDIM * BT);
    transpose_split<<<dim3(BDIM / 32, BDIM / 32, BHEADS), 256>>>(
        VO, (long long)BDIM * BDIM, BDIM, BDIM, vothi, votlo, HD, (long long)BDIM);

    // 1+2) [xq | xk] = x @ [Q;K]^T -> split
    hmma_gemm<1><<<dim3(2 * HR / HTN, MBT / HTM), 256, HMMA_SMEM>>>(
        xhi, xlo, BDIM, qkhi, qklo, BDIM, nullptr,
        xqhi, xqlo, xkhi, xklo, nullptr, HR, BDIM, 1.0f);
    // 3) E = exp(xq @ xk^T / 32) per (b,h) -> hi/lo + partial row sums
    hmma_gemm<3><<<dim3(BT / HTN, BT / HTM, BB * BHEADS), 256, BUFSTRIDE>>>(
        xqhi, xqlo, HR, xkhi, xklo, HR, part,
        phi, plo, nullptr, nullptr, nullptr, BT, BRANK, 0.03125f);
    // 4) reduce partials -> 1/rowsum
    reduce_inv<<<(BB * BHEADS * BT) / 256, 256>>>(part, rinv);
    // 5) ctx = (E @ x) * rinv
    hmma_gemm<4><<<dim3(BDIM / HTN, (BB * BHEADS * BT) / HTM), 256, HMMA_SMEM>>>(
        phi, plo, BT, xthi, xtlo, BT, nullptr,
        ctxhi, ctxlo, nullptr, nullptr, rinv, 0, BT, 1.0f);
    // 6) out partials = ctx @ VO, split-K x4
    hmma_gemm<5><<<dim3(BDIM / HTN, MBT / HTM, SPLITK), 256, HMMA_SMEM>>>(
        ctxhi, ctxlo, HD, vothi, votlo, HD, out4,
        nullptr, nullptr, nullptr, nullptr, nullptr, BDIM, HD / SPLITK, 1.0f);
    // 7) out = sum of partials
    add4<<<(int)(OUTSZ / 4 / 256), 256>>>(out4, out);
}

// round 8
// speedup vs baseline: 1.4931x; 1.4931x over previous
#include <cuda_runtime.h>
#include <cuda_bf16.h>
#include <cstdint>

// Problem constants
#define BDIM   1024
#define BRANK  64
#define BHEADS 16
#define BB     2
#define BT     2048

// ---------------------------------------------------------------------------
// Scratch (device globals)
// ---------------------------------------------------------------------------
__device__ __align__(256) __nv_bfloat16 g_phi[(size_t)BB * BHEADS * BT * BT];
__device__ __align__(256) __nv_bfloat16 g_plo[(size_t)BB * BHEADS * BT * BT];
__device__ __align__(256) float g_part[(size_t)BB * BHEADS * BT * 16];
__device__ __align__(256) float g_rinv[(size_t)BB * BHEADS * BT];
__device__ __align__(256) __nv_bfloat16 g_xhi[(size_t)BB * BT * BDIM];
__device__ __align__(256) __nv_bfloat16 g_xlo[(size_t)BB * BT * BDIM];
__device__ __align__(256) __nv_bfloat16 g_qkhi[(size_t)2 * BHEADS * BRANK * BDIM];
__device__ __align__(256) __nv_bfloat16 g_qklo[(size_t)2 * BHEADS * BRANK * BDIM];
__device__ __align__(256) __nv_bfloat16 g_xqhi[(size_t)BB * BT * BHEADS * BRANK];
__device__ __align__(256) __nv_bfloat16 g_xqlo[(size_t)BB * BT * BHEADS * BRANK];
__device__ __align__(256) __nv_bfloat16 g_xkhi[(size_t)BB * BT * BHEADS * BRANK];
__device__ __align__(256) __nv_bfloat16 g_xklo[(size_t)BB * BT * BHEADS * BRANK];
__device__ __align__(256) __nv_bfloat16 g_xthi[(size_t)BB * BDIM * BT];
__device__ __align__(256) __nv_bfloat16 g_xtlo[(size_t)BB * BDIM * BT];
__device__ __align__(256) __nv_bfloat16 g_ctxhi[(size_t)BB * BT * BHEADS * BDIM];
__device__ __align__(256) __nv_bfloat16 g_ctxlo[(size_t)BB * BT * BHEADS * BDIM];
__device__ __align__(256) __nv_bfloat16 g_vothi[(size_t)BDIM * BHEADS * BDIM];
__device__ __align__(256) __nv_bfloat16 g_votlo[(size_t)BDIM * BHEADS * BDIM];

// ---------------------------------------------------------------------------
// Helpers
// ---------------------------------------------------------------------------
__device__ __forceinline__ uint32_t smem_u32(const void* p) {
    return (uint32_t)__cvta_generic_to_shared(p);
}

#define CP16(s, g) asm volatile("cp.async.cg.shared.global [%0], [%1], 16;" :: "r"(s), "l"(g))

__device__ __forceinline__ void ldsm4(uint32_t* r, uint32_t addr) {
    asm volatile("ldmatrix.sync.aligned.m8n8.x4.shared.b16 {%0,%1,%2,%3}, [%4];"
        : "=r"(r[0]), "=r"(r[1]), "=r"(r[2]), "=r"(r[3]) : "r"(addr));
}

__device__ __forceinline__ void mma16816(float* c, const uint32_t* a, const uint32_t* b) {
    asm volatile("mma.sync.aligned.m16n8k16.row.col.f32.bf16.bf16.f32 "
        "{%0,%1,%2,%3}, {%4,%5,%6,%7}, {%8,%9}, {%0,%1,%2,%3};"
        : "+f"(c[0]), "+f"(c[1]), "+f"(c[2]), "+f"(c[3])
        : "r"(a[0]), "r"(a[1]), "r"(a[2]), "r"(a[3]), "r"(b[0]), "r"(b[1]));
}

template <int N>
__device__ __forceinline__ void cp_wait() {
    asm volatile("cp.async.wait_group %0;" :: "n"(N) : "memory");
}

// ---------------------------------------------------------------------------
// Elementwise hi/lo split
// ---------------------------------------------------------------------------
__global__ __launch_bounds__(256)
void split_f32(const float* __restrict__ in,
               __nv_bfloat16* __restrict__ oh, __nv_bfloat16* __restrict__ ol,
               long long n4)
{
    const long long i = (long long)blockIdx.x * 256 + threadIdx.x;
    if (i >= n4) return;
    float4 v = reinterpret_cast<const float4*>(in)[i];
    __nv_bfloat162 h01, h23, l01, l23;
    h01.x = __float2bfloat16(v.x); h01.y = __float2bfloat16(v.y);
    h23.x = __float2bfloat16(v.z); h23.y = __float2bfloat16(v.w);
    l01.x = __float2bfloat16(v.x - __bfloat162float(h01.x));
    l01.y = __float2bfloat16(v.y - __bfloat162float(h01.y));
    l23.x = __float2bfloat16(v.z - __bfloat162float(h23.x));
    l23.y = __float2bfloat16(v.w - __bfloat162float(h23.y));
    reinterpret_cast<__nv_bfloat162*>(oh)[2 * i + 0] = h01;
    reinterpret_cast<__nv_bfloat162*>(oh)[2 * i + 1] = h23;
    reinterpret_cast<__nv_bfloat162*>(ol)[2 * i + 0] = l01;
    reinterpret_cast<__nv_bfloat162*>(ol)[2 * i + 1] = l23;
}

// ---------------------------------------------------------------------------
// Transpose + hi/lo split: out[c][r] = in[r][c], batched over z (R6 version)
// ---------------------------------------------------------------------------
__global__ __launch_bounds__(256)
void transpose_split(const float* __restrict__ in, long long inBS, int R, int C,
                     __nv_bfloat16* __restrict__ oh, __nv_bfloat16* __restrict__ ol,
                     int oLd, long long oBS)
{
    __shared__ float tile[32][33];
    const int z = blockIdx.z;
    const float* ip = in + (long long)z * inBS;
    const int c0 = blockIdx.x * 32;
    const int r0 = blockIdx.y * 32;
    const int tx = threadIdx.x;
    const int ty = threadIdx.y;

#pragma unroll
    for (int i = 0; i < 32; i += 8)
        tile[ty + i][tx] = ip[(long long)(r0 + ty + i) * C + c0 + tx];
    __syncthreads();

    const long long ob = (long long)z * oBS;
#pragma unroll
    for (int i = 0; i < 32; i += 8) {
        float v = tile[tx][ty + i];
        __nv_bfloat16 h = __float2bfloat16(v);
        float lo = v - __bfloat162float(h);
        long long o = ob + (long long)(c0 + ty + i) * oLd + r0 + tx;
        oh[o] = h;
        ol[o] = __float2bfloat16(lo);
    }
}

// ---------------------------------------------------------------------------
// Reduce 16 per-row partials -> 1/rowsum
// ---------------------------------------------------------------------------
__global__ __launch_bounds__(256)
void reduce_inv(const float* __restrict__ part, float* __restrict__ inv)
{
    const long long r = (long long)blockIdx.x * 256 + threadIdx.x;
    const float4* p = reinterpret_cast<const float4*>(part + r * 16);
    float4 a = p[0], b = p[1], c = p[2], d = p[3];
    float s = ((a.x + a.y) + (a.z + a.w)) + ((b.x + b.y) + (b.z + b.w))
            + ((c.x + c.y) + (c.z + c.w)) + ((d.x + d.y) + (d.z + d.w));
    inv[r] = 1.0f / s;
}

// ---------------------------------------------------------------------------
// HMMA bf16-split GEMM, 3-stage cp.async pipeline, 128x128 tile, KC=64,
// fragment double-buffering (ldsm for ks+1 issued before MMAs of ks).
// STAGE==1: epilogue hi/lo split; ncol<1024 -> xq else xk.
// STAGE==3: z=(b,h); epilogue exp hi/lo -> E + deterministic partial row sums.
// STAGE==4: A=E flat; B=xT per batch; epilogue *= Rinv, ctx hi/lo scatter.
// STAGE==5: epilogue fp32.
// ---------------------------------------------------------------------------
#define HTM 128
#define HTN 128
#define HTK 64

#define BUFSTRIDE 65536
#define AHI_O 0
#define ALO_O 16384
#define BHI_O 32768
#define BLO_O 49152
#define HMMA_SMEM (3 * BUFSTRIDE)   // 192 KB

template <int STAGE>
__global__ __launch_bounds__(256, (STAGE == 3) ? 2 : 1)
void hmma_gemm(const __nv_bfloat16* __restrict__ Ahi, const __nv_bfloat16* __restrict__ Alo,
               int lda,
               const __nv_bfloat16* __restrict__ Bhi, const __nv_bfloat16* __restrict__ Blo,
               int ldb,
               float* __restrict__ Cf,
               __nv_bfloat16* __restrict__ Chi, __nv_bfloat16* __restrict__ Clo,
               __nv_bfloat16* __restrict__ Chi2, __nv_bfloat16* __restrict__ Clo2,
               const float* __restrict__ Rinv,
               int ldc, int K, float alpha)
{
    extern __shared__ char smem[];
    __shared__ float srow[2][HTM];
    const uint32_t sb = smem_u32(smem);
    const int tid  = threadIdx.x;
    const int wid  = tid >> 5;
    const int lane = tid & 31;
    const int mw = wid & 3;
    const int nw = wid >> 2;

    const long long m0 = (long long)blockIdx.y * HTM;
    const int n0 = blockIdx.x * HTN;

    const __nv_bfloat16 *Abh, *Abl, *Bbh, *Bbl;
    if (STAGE == 3) {
        const int z = blockIdx.z;
        const int b = z >> 4;
        const int h = z & 15;
        const long long ao = ((long long)b * BT + m0) * lda + h * BRANK;
        const long long bo = ((long long)b * BT + n0) * ldb + h * BRANK;
        Abh = Ahi + ao;  Abl = Alo + ao;
        Bbh = Bhi + bo;  Bbl = Blo + bo;
    } else if (STAGE == 4) {
        const long long b = m0 >> 15;
        Abh = Ahi + m0 * lda;  Abl = Alo + m0 * lda;
        const long long bo = b * ((long long)BDIM * BT) + (long long)n0 * ldb;
        Bbh = Bhi + bo;  Bbl = Blo + bo;
    } else {
        Abh = Ahi + m0 * lda;  Abl = Alo + m0 * lda;
        Bbh = Bhi + (long long)n0 * ldb;  Bbl = Blo + (long long)n0 * ldb;
    }

    float acc[2][8][4];
#pragma unroll
    for (int i = 0; i < 2; i++)
#pragma unroll
        for (int f = 0; f < 8; f++)
#pragma unroll
            for (int e = 0; e < 4; e++) acc[i][f][e] = 0.0f;

    const int NC = K / HTK;

    auto load_chunk = [&](int c, int buf) {
        const long long kg = (long long)c * HTK;
        const uint32_t bb = sb + buf * BUFSTRIDE;
#pragma unroll
        for (int i = 0; i < 4; i++) {
            const int idx = tid + i * 256;
            const int r  = idx >> 3;
            const int ck = idx & 7;
            const uint32_t so = (uint32_t)(r * 128 + ((ck ^ (r & 7)) << 4));
            const long long ga = (long long)r * lda + kg + ck * 8;
            const long long gb = (long long)r * ldb + kg + ck * 8;
            CP16(bb + AHI_O + so, (const void*)(Abh + ga));
            CP16(bb + ALO_O + so, (const void*)(Abl + ga));
            CP16(bb + BHI_O + so, (const void*)(Bbh + gb));
            CP16(bb + BLO_O + so, (const void*)(Bbl + gb));
        }
        asm volatile("cp.async.commit_group;" ::: "memory");
    };

    load_chunk(0, 0);
    if (NC > 1) load_chunk(1, 1);

    // Double-buffered operand fragments
    uint32_t ah[2][2][4], al[2][2][4], bh[2][4][4], bl[2][4][4];

    for (int c = 0; c < NC; c++) {
        if (c + 2 < NC) load_chunk(c + 2, (c + 2) % 3);
        const int pend = (NC - 1 - c >= 2) ? 2 : (NC - 1 - c);
        if (pend == 2)      cp_wait<2>();
        else if (pend == 1) cp_wait<1>();
        else                cp_wait<0>();
        __syncthreads();

        const uint32_t ab = sb + (c % 3) * BUFSTRIDE;

        auto ldfrag = [&](int ks, int fb) {
#pragma unroll
            for (int i = 0; i < 2; i++) {
                const int r  = mw * 32 + i * 16 + (lane & 15);
                const int ck = ks * 2 + (lane >> 4);
                const uint32_t off = (uint32_t)(r * 128 + ((ck ^ (r & 7)) << 4));
                ldsm4(ah[fb][i], ab + AHI_O + off);
                ldsm4(al[fb][i], ab + ALO_O + off);
            }
#pragma unroll
            for (int j = 0; j < 4; j++) {
                const int r  = nw * 64 + j * 16 + (lane & 7) + ((lane >> 4) & 1) * 8;
                const int ck = ks * 2 + ((lane >> 3) & 1);
                const uint32_t off = (uint32_t)(r * 128 + ((ck ^ (r & 7)) << 4));
                ldsm4(bh[fb][j], ab + BHI_O + off);
                ldsm4(bl[fb][j], ab + BLO_O + off);
            }
        };

        ldfrag(0, 0);
#pragma unroll
        for (int ks = 0; ks < 4; ks++) {
            const int fb = ks & 1;
            if (ks < 3) ldfrag(ks + 1, fb ^ 1);
#pragma unroll
            for (int i = 0; i < 2; i++)
#pragma unroll
                for (int f = 0; f < 8; f++) {
                    const uint32_t* Bh = &bh[fb][f >> 1][(f & 1) * 2];
                    const uint32_t* Bl = &bl[fb][f >> 1][(f & 1) * 2];
                    mma16816(acc[i][f], ah[fb][i], Bh);
                    mma16816(acc[i][f], ah[fb][i], Bl);
                    mma16816(acc[i][f], al[fb][i], Bh);
                }
        }
        __syncthreads();
    }

    // Epilogue
#pragma unroll
    for (int i = 0; i < 2; i++) {
#pragma unroll
        for (int hr = 0; hr < 2; hr++) {
            const long long mg = m0 + mw * 32 + i * 16 + hr * 8 + (lane >> 2);
            const int ncol = n0 + nw * 64 + (lane & 3) * 2;
            if (STAGE == 5) {
                float* dst = Cf + mg * ldc + ncol;
#pragma unroll
                for (int f = 0; f < 8; f++) {
                    float2 v;
                    v.x = acc[i][f][hr * 2 + 0];
                    v.y = acc[i][f][hr * 2 + 1];
                    *reinterpret_cast<float2*>(dst + f * 8) = v;
                }
            } else if (STAGE == 3) {
                const long long orow = (long long)blockIdx.z * BT * BT + mg * ldc + ncol;
                float part = 0.0f;
#pragma unroll
                for (int f = 0; f < 8; f++) {
                    const float e0 = __expf(acc[i][f][hr * 2 + 0] * alpha);
                    const float e1 = __expf(acc[i][f][hr * 2 + 1] * alpha);
                    part += e0 + e1;
                    __nv_bfloat162 hv, lv;
                    hv.x = __float2bfloat16(e0);
                    hv.y = __float2bfloat16(e1);
                    lv.x = __float2bfloat16(e0 - __bfloat162float(hv.x));
                    lv.y = __float2bfloat16(e1 - __bfloat162float(hv.y));
                    *reinterpret_cast<__nv_bfloat162*>(Chi + orow + f * 8) = hv;
                    *reinterpret_cast<__nv_bfloat162*>(Clo + orow + f * 8) = lv;
                }
                part += __shfl_xor_sync(0xffffffffu, part, 1);
                part += __shfl_xor_sync(0xffffffffu, part, 2);
                if ((lane & 3) == 0)
                    srow[nw][mw * 32 + i * 16 + hr * 8 + (lane >> 2)] = part;
            } else if (STAGE == 1) {
                const bool isK = (ncol >= 1024);
                __nv_bfloat16* DH = isK ? Chi2 : Chi;
                __nv_bfloat16* DL = isK ? Clo2 : Clo;
                const long long orow = mg * ldc + (ncol - (isK ? 1024 : 0));
#pragma unroll
                for (int f = 0; f < 8; f++) {
                    const float v0 = acc[i][f][hr * 2 + 0];
                    const float v1 = acc[i][f][hr * 2 + 1];
                    __nv_bfloat162 hv, lv;
                    hv.x = __float2bfloat16(v0);
                    hv.y = __float2bfloat16(v1);
                    lv.x = __float2bfloat16(v0 - __bfloat162float(hv.x));
                    lv.y = __float2bfloat16(v1 - __bfloat162float(hv.y));
                    *reinterpret_cast<__nv_bfloat162*>(DH + orow + f * 8) = hv;
                    *reinterpret_cast<__nv_bfloat162*>(DL + orow + f * 8) = lv;
                }
            } else { // STAGE == 4
                const float rs = Rinv[mg];
                const int b = (int)(mg >> 15);
                const int h = (int)((mg >> 11) & 15);
                const int t = (int)(mg & 2047);
                const long long orow =
                    ((long long)b * BT + t) * ((long long)BHEADS * BDIM) +
                    (long long)h * BDIM + ncol;
#pragma unroll
                for (int f = 0; f < 8; f++) {
                    const float v0 = acc[i][f][hr * 2 + 0] * rs;
                    const float v1 = acc[i][f][hr * 2 + 1] * rs;
                    __nv_bfloat162 hv, lv;
                    hv.x = __float2bfloat16(v0);
                    hv.y = __float2bfloat16(v1);
                    lv.x = __float2bfloat16(v0 - __bfloat162float(hv.x));
                    lv.y = __float2bfloat16(v1 - __bfloat162float(hv.y));
                    *reinterpret_cast<__nv_bfloat162*>(Chi + orow + f * 8) = hv;
                    *reinterpret_cast<__nv_bfloat162*>(Clo + orow + f * 8) = lv;
                }
            }
        }
    }

    if (STAGE == 3) {
        __syncthreads();
        if (tid < HTM) {
            const float s = srow[0][tid] + srow[1][tid];
            Cf[((long long)blockIdx.z * BT + m0 + tid) * 16 + blockIdx.x] = s;
        }
    }
}

// ---------------------------------------------------------------------------
// Launch
// ---------------------------------------------------------------------------
extern "C" void kernel_launch(void* const* d_in, const int* in_sizes, int n_in,
                              void* d_out, int out_size)
{
    const float* x  = (const float*)d_in[0];
    const float* Q  = (const float*)d_in[1];
    const float* K  = (const float*)d_in[2];
    const float* VO = (const float*)d_in[3];
    float* out = (float*)d_out;

    float *part, *rinv;
    __nv_bfloat16 *phi, *plo, *xhi, *xlo, *qkhi, *qklo;
    __nv_bfloat16 *xqhi, *xqlo, *xkhi, *xklo;
    __nv_bfloat16 *xthi, *xtlo, *ctxhi, *ctxlo, *vothi, *votlo;
    cudaGetSymbolAddress((void**)&part,  g_part);
    cudaGetSymbolAddress((void**)&rinv,  g_rinv);
    cudaGetSymbolAddress((void**)&phi,   g_phi);
    cudaGetSymbolAddress((void**)&plo,   g_plo);
    cudaGetSymbolAddress((void**)&xhi,   g_xhi);
    cudaGetSymbolAddress((void**)&xlo,   g_xlo);
    cudaGetSymbolAddress((void**)&qkhi,  g_qkhi);
    cudaGetSymbolAddress((void**)&qklo,  g_qklo);
    cudaGetSymbolAddress((void**)&xqhi,  g_xqhi);
    cudaGetSymbolAddress((void**)&xqlo,  g_xqlo);
    cudaGetSymbolAddress((void**)&xkhi,  g_xkhi);
    cudaGetSymbolAddress((void**)&xklo,  g_xklo);
    cudaGetSymbolAddress((void**)&xthi,  g_xthi);
    cudaGetSymbolAddress((void**)&xtlo,  g_xtlo);
    cudaGetSymbolAddress((void**)&ctxhi, g_ctxhi);
    cudaGetSymbolAddress((void**)&ctxlo, g_ctxlo);
    cudaGetSymbolAddress((void**)&vothi, g_vothi);
    cudaGetSymbolAddress((void**)&votlo, g_votlo);

    cudaFuncSetAttribute(hmma_gemm<1>, cudaFuncAttributeMaxDynamicSharedMemorySize, HMMA_SMEM);
    cudaFuncSetAttribute(hmma_gemm<3>, cudaFuncAttributeMaxDynamicSharedMemorySize, HMMA_SMEM);
    cudaFuncSetAttribute(hmma_gemm<4>, cudaFuncAttributeMaxDynamicSharedMemorySize, HMMA_SMEM);
    cudaFuncSetAttribute(hmma_gemm<5>, cudaFuncAttributeMaxDynamicSharedMemorySize, HMMA_SMEM);

    const int MBT = BB * BT;                  // 4096
    const int HR  = BHEADS * BRANK;           // 1024
    const int HD  = BHEADS * BDIM;            // 16384

    // Input splits (Q and K stacked into one operand)
    split_f32<<<(MBT * BDIM / 4 + 255) / 256, 256>>>(x, xhi, xlo, (long long)MBT * BDIM / 4);
    split_f32<<<(HR * BDIM / 4 + 255) / 256, 256>>>(Q, qkhi, qklo, (long long)HR * BDIM / 4);
    split_f32<<<(HR * BDIM / 4 + 255) / 256, 256>>>(K, qkhi + (size_t)HR * BDIM,
                                                    qklo + (size_t)HR * BDIM,
                                                    (long long)HR * BDIM / 4);
    transpose_split<<<dim3(BDIM / 32, BT / 32, BB), dim3(32, 8)>>>(
        x, (long long)BT * BDIM, BT, BDIM, xthi, xtlo, BT, (long long)BDIM * BT);
    transpose_split<<<dim3(BDIM / 32, BDIM / 32, BHEADS), dim3(32, 8)>>>(
        VO, (long long)BDIM * BDIM, BDIM, BDIM, vothi, votlo, HD, (long long)BDIM);

    // 1+2) [xq | xk] = x @ [Q;K]^T -> split
    hmma_gemm<1><<<dim3(2 * HR / HTN, MBT / HTM), 256, HMMA_SMEM>>>(
        xhi, xlo, BDIM, qkhi, qklo, BDIM, nullptr,
        xqhi, xqlo, xkhi, xklo, nullptr, HR, BDIM, 1.0f);
    // 3) E = exp(xq @ xk^T / 32) per (b,h) -> hi/lo + partial row sums
    hmma_gemm<3><<<dim3(BT / HTN, BT / HTM, BB * BHEADS), 256, BUFSTRIDE>>>(
        xqhi, xqlo, HR, xkhi, xklo, HR, part,
        phi, plo, nullptr, nullptr, nullptr, BT, BRANK, 0.03125f);
    // 4) reduce partials -> 1/rowsum
    reduce_inv<<<(BB * BHEADS * BT) / 256, 256>>>(part, rinv);
    // 5) ctx = (E @ x) * rinv
    hmma_gemm<4><<<dim3(BDIM / HTN, (BB * BHEADS * BT) / HTM), 256, HMMA_SMEM>>>(
        phi, plo, BT, xthi, xtlo, BT, nullptr,
        ctxhi, ctxlo, nullptr, nullptr, rinv, 0, BT, 1.0f);
    // 6) out = ctx @ VO
    hmma_gemm<5><<<dim3(BDIM / HTN, MBT / HTM), 256, HMMA_SMEM>>>(
        ctxhi, ctxlo, HD, vothi, votlo, HD, out,
        nullptr, nullptr, nullptr, nullptr, nullptr, BDIM, HD, 1.0f);
}

// round 9
// speedup vs baseline: 1.8249x; 1.2222x over previous
#include <cuda_runtime.h>
#include <cuda_bf16.h>
#include <cuda_fp16.h>
#include <cstdint>

// Problem constants
#define BDIM   1024
#define BRANK  64
#define BHEADS 16
#define BB     2
#define BT     2048

// ---------------------------------------------------------------------------
// Scratch (device globals)
// ---------------------------------------------------------------------------
__device__ __align__(256) __half g_phi[(size_t)BB * BHEADS * BT * BT];   // E, single fp16
__device__ __align__(256) float g_part[(size_t)BB * BHEADS * BT * 16];
__device__ __align__(256) float g_rinv[(size_t)BB * BHEADS * BT];
__device__ __align__(256) __nv_bfloat16 g_xhi[(size_t)BB * BT * BDIM];
__device__ __align__(256) __nv_bfloat16 g_xlo[(size_t)BB * BT * BDIM];
__device__ __align__(256) __nv_bfloat16 g_qkhi[(size_t)2 * BHEADS * BRANK * BDIM];
__device__ __align__(256) __nv_bfloat16 g_qklo[(size_t)2 * BHEADS * BRANK * BDIM];
__device__ __align__(256) __nv_bfloat16 g_xqhi[(size_t)BB * BT * BHEADS * BRANK];
__device__ __align__(256) __nv_bfloat16 g_xqlo[(size_t)BB * BT * BHEADS * BRANK];
__device__ __align__(256) __nv_bfloat16 g_xkhi[(size_t)BB * BT * BHEADS * BRANK];
__device__ __align__(256) __nv_bfloat16 g_xklo[(size_t)BB * BT * BHEADS * BRANK];
__device__ __align__(256) __half g_xthi[(size_t)BB * BDIM * BT];         // xT fp16 hi
__device__ __align__(256) __half g_xtlo[(size_t)BB * BDIM * BT];         // xT fp16 lo
__device__ __align__(256) __nv_bfloat16 g_ctxhi[(size_t)BB * BT * BHEADS * BDIM];
__device__ __align__(256) __nv_bfloat16 g_ctxlo[(size_t)BB * BT * BHEADS * BDIM];
__device__ __align__(256) __nv_bfloat16 g_vothi[(size_t)BDIM * BHEADS * BDIM];
__device__ __align__(256) __nv_bfloat16 g_votlo[(size_t)BDIM * BHEADS * BDIM];

// ---------------------------------------------------------------------------
// Helpers
// ---------------------------------------------------------------------------
__device__ __forceinline__ uint32_t smem_u32(const void* p) {
    return (uint32_t)__cvta_generic_to_shared(p);
}

#define CP16(s, g) asm volatile("cp.async.cg.shared.global [%0], [%1], 16;" :: "r"(s), "l"(g))

__device__ __forceinline__ void ldsm4(uint32_t* r, uint32_t addr) {
    asm volatile("ldmatrix.sync.aligned.m8n8.x4.shared.b16 {%0,%1,%2,%3}, [%4];"
        : "=r"(r[0]), "=r"(r[1]), "=r"(r[2]), "=r"(r[3]) : "r"(addr));
}

__device__ __forceinline__ void mma16816(float* c, const uint32_t* a, const uint32_t* b) {
    asm volatile("mma.sync.aligned.m16n8k16.row.col.f32.bf16.bf16.f32 "
        "{%0,%1,%2,%3}, {%4,%5,%6,%7}, {%8,%9}, {%0,%1,%2,%3};"
        : "+f"(c[0]), "+f"(c[1]), "+f"(c[2]), "+f"(c[3])
        : "r"(a[0]), "r"(a[1]), "r"(a[2]), "r"(a[3]), "r"(b[0]), "r"(b[1]));
}

__device__ __forceinline__ void mma16816h(float* c, const uint32_t* a, const uint32_t* b) {
    asm volatile("mma.sync.aligned.m16n8k16.row.col.f32.f16.f16.f32 "
        "{%0,%1,%2,%3}, {%4,%5,%6,%7}, {%8,%9}, {%0,%1,%2,%3};"
        : "+f"(c[0]), "+f"(c[1]), "+f"(c[2]), "+f"(c[3])
        : "r"(a[0]), "r"(a[1]), "r"(a[2]), "r"(a[3]), "r"(b[0]), "r"(b[1]));
}

template <int N>
__device__ __forceinline__ void cp_wait() {
    asm volatile("cp.async.wait_group %0;" :: "n"(N) : "memory");
}

// ---------------------------------------------------------------------------
// Elementwise bf16 hi/lo split
// ---------------------------------------------------------------------------
__global__ __launch_bounds__(256)
void split_f32(const float* __restrict__ in,
               __nv_bfloat16* __restrict__ oh, __nv_bfloat16* __restrict__ ol,
               long long n4)
{
    const long long i = (long long)blockIdx.x * 256 + threadIdx.x;
    if (i >= n4) return;
    float4 v = reinterpret_cast<const float4*>(in)[i];
    __nv_bfloat162 h01, h23, l01, l23;
    h01.x = __float2bfloat16(v.x); h01.y = __float2bfloat16(v.y);
    h23.x = __float2bfloat16(v.z); h23.y = __float2bfloat16(v.w);
    l01.x = __float2bfloat16(v.x - __bfloat162float(h01.x));
    l01.y = __float2bfloat16(v.y - __bfloat162float(h01.y));
    l23.x = __float2bfloat16(v.z - __bfloat162float(h23.x));
    l23.y = __float2bfloat16(v.w - __bfloat162float(h23.y));
    reinterpret_cast<__nv_bfloat162*>(oh)[2 * i + 0] = h01;
    reinterpret_cast<__nv_bfloat162*>(oh)[2 * i + 1] = h23;
    reinterpret_cast<__nv_bfloat162*>(ol)[2 * i + 0] = l01;
    reinterpret_cast<__nv_bfloat162*>(ol)[2 * i + 1] = l23;
}

// ---------------------------------------------------------------------------
// Transpose + hi/lo split (templated on output type: bf16 or fp16)
// ---------------------------------------------------------------------------
template <typename T>
__global__ __launch_bounds__(256)
void transpose_split(const float* __restrict__ in, long long inBS, int R, int C,
                     T* __restrict__ oh, T* __restrict__ ol,
                     int oLd, long long oBS)
{
    __shared__ float tile[32][33];
    const int z = blockIdx.z;
    const float* ip = in + (long long)z * inBS;
    const int c0 = blockIdx.x * 32;
    const int r0 = blockIdx.y * 32;
    const int tx = threadIdx.x;
    const int ty = threadIdx.y;

#pragma unroll
    for (int i = 0; i < 32; i += 8)
        tile[ty + i][tx] = ip[(long long)(r0 + ty + i) * C + c0 + tx];
    __syncthreads();

    const long long ob = (long long)z * oBS;
#pragma unroll
    for (int i = 0; i < 32; i += 8) {
        float v = tile[tx][ty + i];
        T h = (T)v;
        float lo = v - (float)h;
        long long o = ob + (long long)(c0 + ty + i) * oLd + r0 + tx;
        oh[o] = h;
        ol[o] = (T)lo;
    }
}

// ---------------------------------------------------------------------------
// Reduce 16 per-row partials -> 1/rowsum
// ---------------------------------------------------------------------------
__global__ __launch_bounds__(256)
void reduce_inv(const float* __restrict__ part, float* __restrict__ inv)
{
    const long long r = (long long)blockIdx.x * 256 + threadIdx.x;
    const float4* p = reinterpret_cast<const float4*>(part + r * 16);
    float4 a = p[0], b = p[1], c = p[2], d = p[3];
    float s = ((a.x + a.y) + (a.z + a.w)) + ((b.x + b.y) + (b.z + b.w))
            + ((c.x + c.y) + (c.z + c.w)) + ((d.x + d.y) + (d.z + d.w));
    inv[r] = 1.0f / s;
}

// ---------------------------------------------------------------------------
// HMMA GEMM, 3-stage cp.async pipeline, 128x128 tile, KC=64.
// STAGE==1: bf16 3-term; epilogue hi/lo split; ncol<1024 -> xq else xk.
// STAGE==3: bf16 3-term; z=(b,h); epilogue exp -> single fp16 E + row sums
//           of the QUANTIZED fp16 values.
// STAGE==4: fp16 2-term (Eh*Xh + Eh*Xl); A=E fp16 flat; B=xT fp16 hi/lo;
//           epilogue *= Rinv, ctx bf16 hi/lo scatter.
// STAGE==5: bf16 3-term; epilogue fp32.
// ---------------------------------------------------------------------------
#define HTM 128
#define HTN 128
#define HTK 64

// bf16 3-term buffer layout (4 tiles) / stage-4 fp16 layout (3 tiles)
#define BUFSTRIDE   65536
#define BUFSTRIDE4  49152
#define HMMA_SMEM   (3 * BUFSTRIDE)    // 192 KB
#define HMMA_SMEM4  (3 * BUFSTRIDE4)   // 144 KB

template <int STAGE>
__global__ __launch_bounds__(256, (STAGE == 3) ? 2 : 1)
void hmma_gemm(const __nv_bfloat16* __restrict__ Ahi, const __nv_bfloat16* __restrict__ Alo,
               int lda,
               const __nv_bfloat16* __restrict__ Bhi, const __nv_bfloat16* __restrict__ Blo,
               int ldb,
               float* __restrict__ Cf,
               __nv_bfloat16* __restrict__ Chi, __nv_bfloat16* __restrict__ Clo,
               __nv_bfloat16* __restrict__ Chi2, __nv_bfloat16* __restrict__ Clo2,
               const float* __restrict__ Rinv,
               int ldc, int K, float alpha)
{
    extern __shared__ char smem[];
    __shared__ float srow[2][HTM];
    const uint32_t sb = smem_u32(smem);
    const int tid  = threadIdx.x;
    const int wid  = tid >> 5;
    const int lane = tid & 31;
    const int mw = wid & 3;
    const int nw = wid >> 2;

    constexpr uint32_t STRIDE = (STAGE == 4) ? BUFSTRIDE4 : BUFSTRIDE;
    constexpr uint32_t ALO_O  = 16384;                       // unused for stage 4
    constexpr uint32_t BHI_O  = (STAGE == 4) ? 16384 : 32768;
    constexpr uint32_t BLO_O  = (STAGE == 4) ? 32768 : 49152;

    const long long m0 = (long long)blockIdx.y * HTM;
    const int n0 = blockIdx.x * HTN;

    const __nv_bfloat16 *Abh, *Abl, *Bbh, *Bbl;
    if (STAGE == 3) {
        const int z = blockIdx.z;
        const int b = z >> 4;
        const int h = z & 15;
        const long long ao = ((long long)b * BT + m0) * lda + h * BRANK;
        const long long bo = ((long long)b * BT + n0) * ldb + h * BRANK;
        Abh = Ahi + ao;  Abl = Alo + ao;
        Bbh = Bhi + bo;  Bbl = Blo + bo;
    } else if (STAGE == 4) {
        const long long b = m0 >> 15;
        Abh = Ahi + m0 * lda;  Abl = nullptr;
        const long long bo = b * ((long long)BDIM * BT) + (long long)n0 * ldb;
        Bbh = Bhi + bo;  Bbl = Blo + bo;
    } else {
        Abh = Ahi + m0 * lda;  Abl = Alo + m0 * lda;
        Bbh = Bhi + (long long)n0 * ldb;  Bbl = Blo + (long long)n0 * ldb;
    }

    float acc[2][8][4];
#pragma unroll
    for (int i = 0; i < 2; i++)
#pragma unroll
        for (int f = 0; f < 8; f++)
#pragma unroll
            for (int e = 0; e < 4; e++) acc[i][f][e] = 0.0f;

    const int NC = K / HTK;

    auto load_chunk = [&](int c, int buf) {
        const long long kg = (long long)c * HTK;
        const uint32_t bb = sb + buf * STRIDE;
#pragma unroll
        for (int i = 0; i < 4; i++) {
            const int idx = tid + i * 256;
            const int r  = idx >> 3;
            const int ck = idx & 7;
            const uint32_t so = (uint32_t)(r * 128 + ((ck ^ (r & 7)) << 4));
            const long long ga = (long long)r * lda + kg + ck * 8;
            const long long gb = (long long)r * ldb + kg + ck * 8;
            CP16(bb + so, (const void*)(Abh + ga));
            if (STAGE != 4) CP16(bb + ALO_O + so, (const void*)(Abl + ga));
            CP16(bb + BHI_O + so, (const void*)(Bbh + gb));
            CP16(bb + BLO_O + so, (const void*)(Bbl + gb));
        }
        asm volatile("cp.async.commit_group;" ::: "memory");
    };

    load_chunk(0, 0);
    if (NC > 1) load_chunk(1, 1);

    for (int c = 0; c < NC; c++) {
        if (c + 2 < NC) load_chunk(c + 2, (c + 2) % 3);
        const int pend = (NC - 1 - c >= 2) ? 2 : (NC - 1 - c);
        if (pend == 2)      cp_wait<2>();
        else if (pend == 1) cp_wait<1>();
        else                cp_wait<0>();
        __syncthreads();

        const uint32_t ab = sb + (c % 3) * STRIDE;
#pragma unroll
        for (int ks = 0; ks < 4; ks++) {
            uint32_t ah[2][4], al[2][4], bh[4][4], bl[4][4];
#pragma unroll
            for (int i = 0; i < 2; i++) {
                const int r  = mw * 32 + i * 16 + (lane & 15);
                const int ck = ks * 2 + (lane >> 4);
                const uint32_t off = (uint32_t)(r * 128 + ((ck ^ (r & 7)) << 4));
                ldsm4(ah[i], ab + off);
                if (STAGE != 4) ldsm4(al[i], ab + ALO_O + off);
            }
#pragma unroll
            for (int j = 0; j < 4; j++) {
                const int r  = nw * 64 + j * 16 + (lane & 7) + ((lane >> 4) & 1) * 8;
                const int ck = ks * 2 + ((lane >> 3) & 1);
                const uint32_t off = (uint32_t)(r * 128 + ((ck ^ (r & 7)) << 4));
                ldsm4(bh[j], ab + BHI_O + off);
                ldsm4(bl[j], ab + BLO_O + off);
            }
#pragma unroll
            for (int i = 0; i < 2; i++)
#pragma unroll
                for (int f = 0; f < 8; f++) {
                    const uint32_t* Bh = &bh[f >> 1][(f & 1) * 2];
                    const uint32_t* Bl = &bl[f >> 1][(f & 1) * 2];
                    if (STAGE == 4) {
                        mma16816h(acc[i][f], ah[i], Bh);
                        mma16816h(acc[i][f], ah[i], Bl);
                    } else {
                        mma16816(acc[i][f], ah[i], Bh);
                        mma16816(acc[i][f], ah[i], Bl);
                        mma16816(acc[i][f], al[i], Bh);
                    }
                }
        }
        __syncthreads();
    }

    // Epilogue
#pragma unroll
    for (int i = 0; i < 2; i++) {
#pragma unroll
        for (int hr = 0; hr < 2; hr++) {
            const long long mg = m0 + mw * 32 + i * 16 + hr * 8 + (lane >> 2);
            const int ncol = n0 + nw * 64 + (lane & 3) * 2;
            if (STAGE == 5) {
                float* dst = Cf + mg * ldc + ncol;
#pragma unroll
                for (int f = 0; f < 8; f++) {
                    float2 v;
                    v.x = acc[i][f][hr * 2 + 0];
                    v.y = acc[i][f][hr * 2 + 1];
                    *reinterpret_cast<float2*>(dst + f * 8) = v;
                }
            } else if (STAGE == 3) {
                // E = exp(score) -> single fp16; rowsum of QUANTIZED values
                const long long orow = (long long)blockIdx.z * BT * BT + mg * ldc + ncol;
                float part = 0.0f;
#pragma unroll
                for (int f = 0; f < 8; f++) {
                    const float e0 = __expf(acc[i][f][hr * 2 + 0] * alpha);
                    const float e1 = __expf(acc[i][f][hr * 2 + 1] * alpha);
                    __half2 hv;
                    hv.x = __float2half(e0);
                    hv.y = __float2half(e1);
                    part += __half2float(hv.x) + __half2float(hv.y);
                    *reinterpret_cast<__half2*>(
                        reinterpret_cast<__half*>(Chi) + orow + f * 8) = hv;
                }
                part += __shfl_xor_sync(0xffffffffu, part, 1);
                part += __shfl_xor_sync(0xffffffffu, part, 2);
                if ((lane & 3) == 0)
                    srow[nw][mw * 32 + i * 16 + hr * 8 + (lane >> 2)] = part;
            } else if (STAGE == 1) {
                const bool isK = (ncol >= 1024);
                __nv_bfloat16* DH = isK ? Chi2 : Chi;
                __nv_bfloat16* DL = isK ? Clo2 : Clo;
                const long long orow = mg * ldc + (ncol - (isK ? 1024 : 0));
#pragma unroll
                for (int f = 0; f < 8; f++) {
                    const float v0 = acc[i][f][hr * 2 + 0];
                    const float v1 = acc[i][f][hr * 2 + 1];
                    __nv_bfloat162 hv, lv;
                    hv.x = __float2bfloat16(v0);
                    hv.y = __float2bfloat16(v1);
                    lv.x = __float2bfloat16(v0 - __bfloat162float(hv.x));
                    lv.y = __float2bfloat16(v1 - __bfloat162float(hv.y));
                    *reinterpret_cast<__nv_bfloat162*>(DH + orow + f * 8) = hv;
                    *reinterpret_cast<__nv_bfloat162*>(DL + orow + f * 8) = lv;
                }
            } else { // STAGE == 4
                const float rs = Rinv[mg];
                const int b = (int)(mg >> 15);
                const int h = (int)((mg >> 11) & 15);
                const int t = (int)(mg & 2047);
                const long long orow =
                    ((long long)b * BT + t) * ((long long)BHEADS * BDIM) +
                    (long long)h * BDIM + ncol;
#pragma unroll
                for (int f = 0; f < 8; f++) {
                    const float v0 = acc[i][f][hr * 2 + 0] * rs;
                    const float v1 = acc[i][f][hr * 2 + 1] * rs;
                    __nv_bfloat162 hv, lv;
                    hv.x = __float2bfloat16(v0);
                    hv.y = __float2bfloat16(v1);
                    lv.x = __float2bfloat16(v0 - __bfloat162float(hv.x));
                    lv.y = __float2bfloat16(v1 - __bfloat162float(hv.y));
                    *reinterpret_cast<__nv_bfloat162*>(Chi + orow + f * 8) = hv;
                    *reinterpret_cast<__nv_bfloat162*>(Clo + orow + f * 8) = lv;
                }
            }
        }
    }

    if (STAGE == 3) {
        __syncthreads();
        if (tid < HTM) {
            const float s = srow[0][tid] + srow[1][tid];
            Cf[((long long)blockIdx.z * BT + m0 + tid) * 16 + blockIdx.x] = s;
        }
    }
}

// ---------------------------------------------------------------------------
// Launch
// ---------------------------------------------------------------------------
extern "C" void kernel_launch(void* const* d_in, const int* in_sizes, int n_in,
                              void* d_out, int out_size)
{
    const float* x  = (const float*)d_in[0];
    const float* Q  = (const float*)d_in[1];
    const float* K  = (const float*)d_in[2];
    const float* VO = (const float*)d_in[3];
    float* out = (float*)d_out;

    float *part, *rinv;
    __half *phi, *xthi, *xtlo;
    __nv_bfloat16 *xhi, *xlo, *qkhi, *qklo;
    __nv_bfloat16 *xqhi, *xqlo, *xkhi, *xklo;
    __nv_bfloat16 *ctxhi, *ctxlo, *vothi, *votlo;
    cudaGetSymbolAddress((void**)&part,  g_part);
    cudaGetSymbolAddress((void**)&rinv,  g_rinv);
    cudaGetSymbolAddress((void**)&phi,   g_phi);
    cudaGetSymbolAddress((void**)&xhi,   g_xhi);
    cudaGetSymbolAddress((void**)&xlo,   g_xlo);
    cudaGetSymbolAddress((void**)&qkhi,  g_qkhi);
    cudaGetSymbolAddress((void**)&qklo,  g_qklo);
    cudaGetSymbolAddress((void**)&xqhi,  g_xqhi);
    cudaGetSymbolAddress((void**)&xqlo,  g_xqlo);
    cudaGetSymbolAddress((void**)&xkhi,  g_xkhi);
    cudaGetSymbolAddress((void**)&xklo,  g_xklo);
    cudaGetSymbolAddress((void**)&xthi,  g_xthi);
    cudaGetSymbolAddress((void**)&xtlo,  g_xtlo);
    cudaGetSymbolAddress((void**)&ctxhi, g_ctxhi);
    cudaGetSymbolAddress((void**)&ctxlo, g_ctxlo);
    cudaGetSymbolAddress((void**)&vothi, g_vothi);
    cudaGetSymbolAddress((void**)&votlo, g_votlo);

    cudaFuncSetAttribute(hmma_gemm<1>, cudaFuncAttributeMaxDynamicSharedMemorySize, HMMA_SMEM);
    cudaFuncSetAttribute(hmma_gemm<3>, cudaFuncAttributeMaxDynamicSharedMemorySize, HMMA_SMEM);
    cudaFuncSetAttribute(hmma_gemm<4>, cudaFuncAttributeMaxDynamicSharedMemorySize, HMMA_SMEM4);
    cudaFuncSetAttribute(hmma_gemm<5>, cudaFuncAttributeMaxDynamicSharedMemorySize, HMMA_SMEM);

    const int MBT = BB * BT;                  // 4096
    const int HR  = BHEADS * BRANK;           // 1024
    const int HD  = BHEADS * BDIM;            // 16384

    // Input splits (Q and K stacked into one operand)
    split_f32<<<(MBT * BDIM / 4 + 255) / 256, 256>>>(x, xhi, xlo, (long long)MBT * BDIM / 4);
    split_f32<<<(HR * BDIM / 4 + 255) / 256, 256>>>(Q, qkhi, qklo, (long long)HR * BDIM / 4);
    split_f32<<<(HR * BDIM / 4 + 255) / 256, 256>>>(K, qkhi + (size_t)HR * BDIM,
                                                    qklo + (size_t)HR * BDIM,
                                                    (long long)HR * BDIM / 4);
    transpose_split<__half><<<dim3(BDIM / 32, BT / 32, BB), dim3(32, 8)>>>(
        x, (long long)BT * BDIM, BT, BDIM, xthi, xtlo, BT, (long long)BDIM * BT);
    transpose_split<__nv_bfloat16><<<dim3(BDIM / 32, BDIM / 32, BHEADS), dim3(32, 8)>>>(
        VO, (long long)BDIM * BDIM, BDIM, BDIM, vothi, votlo, HD, (long long)BDIM);

    // 1+2) [xq | xk] = x @ [Q;K]^T -> split
    hmma_gemm<1><<<dim3(2 * HR / HTN, MBT / HTM), 256, HMMA_SMEM>>>(
        xhi, xlo, BDIM, qkhi, qklo, BDIM, nullptr,
        xqhi, xqlo, xkhi, xklo, nullptr, HR, BDIM, 1.0f);
    // 3) E = exp(xq @ xk^T / 32) per (b,h) -> single fp16 + quantized row sums
    hmma_gemm<3><<<dim3(BT / HTN, BT / HTM, BB * BHEADS), 256, BUFSTRIDE>>>(
        xqhi, xqlo, HR, xkhi, xklo, HR, part,
        (__nv_bfloat16*)phi, nullptr, nullptr, nullptr, nullptr, BT, BRANK, 0.03125f);
    // 4) reduce partials -> 1/rowsum
    reduce_inv<<<(BB * BHEADS * BT) / 256, 256>>>(part, rinv);
    // 5) ctx = (E @ x) * rinv   (fp16 2-term)
    hmma_gemm<4><<<dim3(BDIM / HTN, (BB * BHEADS * BT) / HTM), 256, HMMA_SMEM4>>>(
        (const __nv_bfloat16*)phi, nullptr, BT,
        (const __nv_bfloat16*)xthi, (const __nv_bfloat16*)xtlo, BT, nullptr,
        ctxhi, ctxlo, nullptr, nullptr, rinv, 0, BT, 1.0f);
    // 6) out = ctx @ VO   (bf16 3-term)
    hmma_gemm<5><<<dim3(BDIM / HTN, MBT / HTM), 256, HMMA_SMEM>>>(
        ctxhi, ctxlo, HD, vothi, votlo, HD, out,
        nullptr, nullptr, nullptr, nullptr, nullptr, BDIM, HD, 1.0f);
}

// round 10
// speedup vs baseline: 2.1109x; 1.1567x over previous
#include <cuda_runtime.h>
#include <cuda_bf16.h>
#include <cuda_fp16.h>
#include <cstdint>

// Problem constants
#define BDIM   1024
#define BRANK  64
#define BHEADS 16
#define BB     2
#define BT     2048

// ---------------------------------------------------------------------------
// Scratch (device globals)
// ---------------------------------------------------------------------------
__device__ __align__(256) __half g_phi[(size_t)BB * BHEADS * BT * BT];   // E, single fp16
__device__ __align__(256) float g_part[(size_t)BB * BHEADS * BT * 16];
__device__ __align__(256) float g_rinv[(size_t)BB * BHEADS * BT];
__device__ __align__(256) __nv_bfloat16 g_xhi[(size_t)BB * BT * BDIM];
__device__ __align__(256) __nv_bfloat16 g_xlo[(size_t)BB * BT * BDIM];
__device__ __align__(256) __nv_bfloat16 g_qkhi[(size_t)2 * BHEADS * BRANK * BDIM];
__device__ __align__(256) __nv_bfloat16 g_qklo[(size_t)2 * BHEADS * BRANK * BDIM];
__device__ __align__(256) __nv_bfloat16 g_xqhi[(size_t)BB * BT * BHEADS * BRANK];
__device__ __align__(256) __nv_bfloat16 g_xqlo[(size_t)BB * BT * BHEADS * BRANK];
__device__ __align__(256) __nv_bfloat16 g_xkhi[(size_t)BB * BT * BHEADS * BRANK];
__device__ __align__(256) __nv_bfloat16 g_xklo[(size_t)BB * BT * BHEADS * BRANK];
__device__ __align__(256) __half g_xthi[(size_t)BB * BDIM * BT];         // xT fp16 hi
__device__ __align__(256) __half g_xtlo[(size_t)BB * BDIM * BT];         // xT fp16 lo
__device__ __align__(256) __half g_ctx[(size_t)BB * BT * BHEADS * BDIM]; // ctx single fp16
__device__ __align__(256) __half g_vothi[(size_t)BDIM * BHEADS * BDIM];  // VOT fp16 hi
__device__ __align__(256) __half g_votlo[(size_t)BDIM * BHEADS * BDIM];  // VOT fp16 lo

// ---------------------------------------------------------------------------
// Helpers
// ---------------------------------------------------------------------------
__device__ __forceinline__ uint32_t smem_u32(const void* p) {
    return (uint32_t)__cvta_generic_to_shared(p);
}

#define CP16(s, g) asm volatile("cp.async.cg.shared.global [%0], [%1], 16;" :: "r"(s), "l"(g))

__device__ __forceinline__ void ldsm4(uint32_t* r, uint32_t addr) {
    asm volatile("ldmatrix.sync.aligned.m8n8.x4.shared.b16 {%0,%1,%2,%3}, [%4];"
        : "=r"(r[0]), "=r"(r[1]), "=r"(r[2]), "=r"(r[3]) : "r"(addr));
}

__device__ __forceinline__ void mma16816(float* c, const uint32_t* a, const uint32_t* b) {
    asm volatile("mma.sync.aligned.m16n8k16.row.col.f32.bf16.bf16.f32 "
        "{%0,%1,%2,%3}, {%4,%5,%6,%7}, {%8,%9}, {%0,%1,%2,%3};"
        : "+f"(c[0]), "+f"(c[1]), "+f"(c[2]), "+f"(c[3])
        : "r"(a[0]), "r"(a[1]), "r"(a[2]), "r"(a[3]), "r"(b[0]), "r"(b[1]));
}

__device__ __forceinline__ void mma16816h(float* c, const uint32_t* a, const uint32_t* b) {
    asm volatile("mma.sync.aligned.m16n8k16.row.col.f32.f16.f16.f32 "
        "{%0,%1,%2,%3}, {%4,%5,%6,%7}, {%8,%9}, {%0,%1,%2,%3};"
        : "+f"(c[0]), "+f"(c[1]), "+f"(c[2]), "+f"(c[3])
        : "r"(a[0]), "r"(a[1]), "r"(a[2]), "r"(a[3]), "r"(b[0]), "r"(b[1]));
}

template <int N>
__device__ __forceinline__ void cp_wait() {
    asm volatile("cp.async.wait_group %0;" :: "n"(N) : "memory");
}

// ---------------------------------------------------------------------------
// Elementwise bf16 hi/lo split
// ---------------------------------------------------------------------------
__global__ __launch_bounds__(256)
void split_f32(const float* __restrict__ in,
               __nv_bfloat16* __restrict__ oh, __nv_bfloat16* __restrict__ ol,
               long long n4)
{
    const long long i = (long long)blockIdx.x * 256 + threadIdx.x;
    if (i >= n4) return;
    float4 v = reinterpret_cast<const float4*>(in)[i];
    __nv_bfloat162 h01, h23, l01, l23;
    h01.x = __float2bfloat16(v.x); h01.y = __float2bfloat16(v.y);
    h23.x = __float2bfloat16(v.z); h23.y = __float2bfloat16(v.w);
    l01.x = __float2bfloat16(v.x - __bfloat162float(h01.x));
    l01.y = __float2bfloat16(v.y - __bfloat162float(h01.y));
    l23.x = __float2bfloat16(v.z - __bfloat162float(h23.x));
    l23.y = __float2bfloat16(v.w - __bfloat162float(h23.y));
    reinterpret_cast<__nv_bfloat162*>(oh)[2 * i + 0] = h01;
    reinterpret_cast<__nv_bfloat162*>(oh)[2 * i + 1] = h23;
    reinterpret_cast<__nv_bfloat162*>(ol)[2 * i + 0] = l01;
    reinterpret_cast<__nv_bfloat162*>(ol)[2 * i + 1] = l23;
}

// ---------------------------------------------------------------------------
// Transpose + hi/lo split (templated output type)
// ---------------------------------------------------------------------------
template <typename T>
__global__ __launch_bounds__(256)
void transpose_split(const float* __restrict__ in, long long inBS, int R, int C,
                     T* __restrict__ oh, T* __restrict__ ol,
                     int oLd, long long oBS)
{
    __shared__ float tile[32][33];
    const int z = blockIdx.z;
    const float* ip = in + (long long)z * inBS;
    const int c0 = blockIdx.x * 32;
    const int r0 = blockIdx.y * 32;
    const int tx = threadIdx.x;
    const int ty = threadIdx.y;

#pragma unroll
    for (int i = 0; i < 32; i += 8)
        tile[ty + i][tx] = ip[(long long)(r0 + ty + i) * C + c0 + tx];
    __syncthreads();

    const long long ob = (long long)z * oBS;
#pragma unroll
    for (int i = 0; i < 32; i += 8) {
        float v = tile[tx][ty + i];
        T h = (T)v;
        float lo = v - (float)h;
        long long o = ob + (long long)(c0 + ty + i) * oLd + r0 + tx;
        oh[o] = h;
        ol[o] = (T)lo;
    }
}

// ---------------------------------------------------------------------------
// Reduce 16 per-row partials -> 1/rowsum
// ---------------------------------------------------------------------------
__global__ __launch_bounds__(256)
void reduce_inv(const float* __restrict__ part, float* __restrict__ inv)
{
    const long long r = (long long)blockIdx.x * 256 + threadIdx.x;
    const float4* p = reinterpret_cast<const float4*>(part + r * 16);
    float4 a = p[0], b = p[1], c = p[2], d = p[3];
    float s = ((a.x + a.y) + (a.z + a.w)) + ((b.x + b.y) + (b.z + b.w))
            + ((c.x + c.y) + (c.z + c.w)) + ((d.x + d.y) + (d.z + d.w));
    inv[r] = 1.0f / s;
}

// ---------------------------------------------------------------------------
// HMMA GEMM, 3-stage cp.async pipeline, 128x128 tile, KC=64.
// STAGE==1: bf16 3-term; epilogue hi/lo split; ncol<1024 -> xq else xk.
// STAGE==3: bf16 3-term; z=(b,h); epilogue exp -> single fp16 E + row sums
//           of the QUANTIZED fp16 values.
// STAGE==4: fp16 2-term (E*Xh + E*Xl); epilogue *= Rinv, ctx single fp16 scatter.
// STAGE==5: fp16 2-term (ctx*Vh + ctx*Vl); epilogue fp32.
// ---------------------------------------------------------------------------
#define HTM 128
#define HTN 128
#define HTK 64

#define BUFSTRIDE   65536   // 4 tiles (bf16 3-term)
#define BUFSTRIDE4  49152   // 3 tiles (fp16 2-term)
#define HMMA_SMEM   (3 * BUFSTRIDE)    // 192 KB
#define HMMA_SMEM4  (3 * BUFSTRIDE4)   // 144 KB

template <int STAGE>
__global__ __launch_bounds__(256, (STAGE == 3) ? 2 : 1)
void hmma_gemm(const __nv_bfloat16* __restrict__ Ahi, const __nv_bfloat16* __restrict__ Alo,
               int lda,
               const __nv_bfloat16* __restrict__ Bhi, const __nv_bfloat16* __restrict__ Blo,
               int ldb,
               float* __restrict__ Cf,
               __nv_bfloat16* __restrict__ Chi, __nv_bfloat16* __restrict__ Clo,
               __nv_bfloat16* __restrict__ Chi2, __nv_bfloat16* __restrict__ Clo2,
               const float* __restrict__ Rinv,
               int ldc, int K, float alpha)
{
    extern __shared__ char smem[];
    __shared__ float srow[2][HTM];
    const uint32_t sb = smem_u32(smem);
    const int tid  = threadIdx.x;
    const int wid  = tid >> 5;
    const int lane = tid & 31;
    const int mw = wid & 3;
    const int nw = wid >> 2;

    constexpr bool FP16MODE = (STAGE >= 4);
    constexpr uint32_t STRIDE = FP16MODE ? BUFSTRIDE4 : BUFSTRIDE;
    constexpr uint32_t ALO_O  = 16384;
    constexpr uint32_t BHI_O  = FP16MODE ? 16384 : 32768;
    constexpr uint32_t BLO_O  = FP16MODE ? 32768 : 49152;

    const long long m0 = (long long)blockIdx.y * HTM;
    const int n0 = blockIdx.x * HTN;

    const __nv_bfloat16 *Abh, *Abl, *Bbh, *Bbl;
    if (STAGE == 3) {
        const int z = blockIdx.z;
        const int b = z >> 4;
        const int h = z & 15;
        const long long ao = ((long long)b * BT + m0) * lda + h * BRANK;
        const long long bo = ((long long)b * BT + n0) * ldb + h * BRANK;
        Abh = Ahi + ao;  Abl = Alo + ao;
        Bbh = Bhi + bo;  Bbl = Blo + bo;
    } else if (STAGE == 4) {
        const long long b = m0 >> 15;
        Abh = Ahi + m0 * lda;  Abl = nullptr;
        const long long bo = b * ((long long)BDIM * BT) + (long long)n0 * ldb;
        Bbh = Bhi + bo;  Bbl = Blo + bo;
    } else {
        Abh = Ahi + m0 * lda;  Abl = (STAGE == 5) ? nullptr : Alo + m0 * lda;
        Bbh = Bhi + (long long)n0 * ldb;  Bbl = Blo + (long long)n0 * ldb;
    }

    float acc[2][8][4];
#pragma unroll
    for (int i = 0; i < 2; i++)
#pragma unroll
        for (int f = 0; f < 8; f++)
#pragma unroll
            for (int e = 0; e < 4; e++) acc[i][f][e] = 0.0f;

    const int NC = K / HTK;

    auto load_chunk = [&](int c, int buf) {
        const long long kg = (long long)c * HTK;
        const uint32_t bb = sb + buf * STRIDE;
#pragma unroll
        for (int i = 0; i < 4; i++) {
            const int idx = tid + i * 256;
            const int r  = idx >> 3;
            const int ck = idx & 7;
            const uint32_t so = (uint32_t)(r * 128 + ((ck ^ (r & 7)) << 4));
            const long long ga = (long long)r * lda + kg + ck * 8;
            const long long gb = (long long)r * ldb + kg + ck * 8;
            CP16(bb + so, (const void*)(Abh + ga));
            if (!FP16MODE) CP16(bb + ALO_O + so, (const void*)(Abl + ga));
            CP16(bb + BHI_O + so, (const void*)(Bbh + gb));
            CP16(bb + BLO_O + so, (const void*)(Bbl + gb));
        }
        asm volatile("cp.async.commit_group;" ::: "memory");
    };

    load_chunk(0, 0);
    if (NC > 1) load_chunk(1, 1);

    for (int c = 0; c < NC; c++) {
        if (c + 2 < NC) load_chunk(c + 2, (c + 2) % 3);
        const int pend = (NC - 1 - c >= 2) ? 2 : (NC - 1 - c);
        if (pend == 2)      cp_wait<2>();
        else if (pend == 1) cp_wait<1>();
        else                cp_wait<0>();
        __syncthreads();

        const uint32_t ab = sb + (c % 3) * STRIDE;
#pragma unroll
        for (int ks = 0; ks < 4; ks++) {
            uint32_t ah[2][4], al[2][4], bh[4][4], bl[4][4];
#pragma unroll
            for (int i = 0; i < 2; i++) {
                const int r  = mw * 32 + i * 16 + (lane & 15);
                const int ck = ks * 2 + (lane >> 4);
                const uint32_t off = (uint32_t)(r * 128 + ((ck ^ (r & 7)) << 4));
                ldsm4(ah[i], ab + off);
                if (!FP16MODE) ldsm4(al[i], ab + ALO_O + off);
            }
#pragma unroll
            for (int j = 0; j < 4; j++) {
                const int r  = nw * 64 + j * 16 + (lane & 7) + ((lane >> 4) & 1) * 8;
                const int ck = ks * 2 + ((lane >> 3) & 1);
                const uint32_t off = (uint32_t)(r * 128 + ((ck ^ (r & 7)) << 4));
                ldsm4(bh[j], ab + BHI_O + off);
                ldsm4(bl[j], ab + BLO_O + off);
            }
#pragma unroll
            for (int i = 0; i < 2; i++)
#pragma unroll
                for (int f = 0; f < 8; f++) {
                    const uint32_t* Bh = &bh[f >> 1][(f & 1) * 2];
                    const uint32_t* Bl = &bl[f >> 1][(f & 1) * 2];
                    if (FP16MODE) {
                        mma16816h(acc[i][f], ah[i], Bh);
                        mma16816h(acc[i][f], ah[i], Bl);
                    } else {
                        mma16816(acc[i][f], ah[i], Bh);
                        mma16816(acc[i][f], ah[i], Bl);
                        mma16816(acc[i][f], al[i], Bh);
                    }
                }
        }
        __syncthreads();
    }

    // Epilogue
#pragma unroll
    for (int i = 0; i < 2; i++) {
#pragma unroll
        for (int hr = 0; hr < 2; hr++) {
            const long long mg = m0 + mw * 32 + i * 16 + hr * 8 + (lane >> 2);
            const int ncol = n0 + nw * 64 + (lane & 3) * 2;
            if (STAGE == 5) {
                float* dst = Cf + mg * ldc + ncol;
#pragma unroll
                for (int f = 0; f < 8; f++) {
                    float2 v;
                    v.x = acc[i][f][hr * 2 + 0];
                    v.y = acc[i][f][hr * 2 + 1];
                    *reinterpret_cast<float2*>(dst + f * 8) = v;
                }
            } else if (STAGE == 3) {
                // E = exp(score) -> single fp16; rowsum of QUANTIZED values
                const long long orow = (long long)blockIdx.z * BT * BT + mg * ldc + ncol;
                float part = 0.0f;
#pragma unroll
                for (int f = 0; f < 8; f++) {
                    const float e0 = __expf(acc[i][f][hr * 2 + 0] * alpha);
                    const float e1 = __expf(acc[i][f][hr * 2 + 1] * alpha);
                    __half2 hv;
                    hv.x = __float2half(e0);
                    hv.y = __float2half(e1);
                    part += __half2float(hv.x) + __half2float(hv.y);
                    *reinterpret_cast<__half2*>(
                        reinterpret_cast<__half*>(Chi) + orow + f * 8) = hv;
                }
                part += __shfl_xor_sync(0xffffffffu, part, 1);
                part += __shfl_xor_sync(0xffffffffu, part, 2);
                if ((lane & 3) == 0)
                    srow[nw][mw * 32 + i * 16 + hr * 8 + (lane >> 2)] = part;
            } else if (STAGE == 1) {
                const bool isK = (ncol >= 1024);
                __nv_bfloat16* DH = isK ? Chi2 : Chi;
                __nv_bfloat16* DL = isK ? Clo2 : Clo;
                const long long orow = mg * ldc + (ncol - (isK ? 1024 : 0));
#pragma unroll
                for (int f = 0; f < 8; f++) {
                    const float v0 = acc[i][f][hr * 2 + 0];
                    const float v1 = acc[i][f][hr * 2 + 1];
                    __nv_bfloat162 hv, lv;
                    hv.x = __float2bfloat16(v0);
                    hv.y = __float2bfloat16(v1);
                    lv.x = __float2bfloat16(v0 - __bfloat162float(hv.x));
                    lv.y = __float2bfloat16(v1 - __bfloat162float(hv.y));
                    *reinterpret_cast<__nv_bfloat162*>(DH + orow + f * 8) = hv;
                    *reinterpret_cast<__nv_bfloat162*>(DL + orow + f * 8) = lv;
                }
            } else { // STAGE == 4 : ctx single fp16
                const float rs = Rinv[mg];
                const int b = (int)(mg >> 15);
                const int h = (int)((mg >> 11) & 15);
                const int t = (int)(mg & 2047);
                const long long orow =
                    ((long long)b * BT + t) * ((long long)BHEADS * BDIM) +
                    (long long)h * BDIM + ncol;
                __half* dst = reinterpret_cast<__half*>(Chi);
#pragma unroll
                for (int f = 0; f < 8; f++) {
                    __half2 hv;
                    hv.x = __float2half(acc[i][f][hr * 2 + 0] * rs);
                    hv.y = __float2half(acc[i][f][hr * 2 + 1] * rs);
                    *reinterpret_cast<__half2*>(dst + orow + f * 8) = hv;
                }
            }
        }
    }

    if (STAGE == 3) {
        __syncthreads();
        if (tid < HTM) {
            const float s = srow[0][tid] + srow[1][tid];
            Cf[((long long)blockIdx.z * BT + m0 + tid) * 16 + blockIdx.x] = s;
        }
    }
}

// ---------------------------------------------------------------------------
// Launch
// ---------------------------------------------------------------------------
extern "C" void kernel_launch(void* const* d_in, const int* in_sizes, int n_in,
                              void* d_out, int out_size)
{
    const float* x  = (const float*)d_in[0];
    const float* Q  = (const float*)d_in[1];
    const float* K  = (const float*)d_in[2];
    const float* VO = (const float*)d_in[3];
    float* out = (float*)d_out;

    float *part, *rinv;
    __half *phi, *xthi, *xtlo, *ctx, *vothi, *votlo;
    __nv_bfloat16 *xhi, *xlo, *qkhi, *qklo;
    __nv_bfloat16 *xqhi, *xqlo, *xkhi, *xklo;
    cudaGetSymbolAddress((void**)&part,  g_part);
    cudaGetSymbolAddress((void**)&rinv,  g_rinv);
    cudaGetSymbolAddress((void**)&phi,   g_phi);
    cudaGetSymbolAddress((void**)&xhi,   g_xhi);
    cudaGetSymbolAddress((void**)&xlo,   g_xlo);
    cudaGetSymbolAddress((void**)&qkhi,  g_qkhi);
    cudaGetSymbolAddress((void**)&qklo,  g_qklo);
    cudaGetSymbolAddress((void**)&xqhi,  g_xqhi);
    cudaGetSymbolAddress((void**)&xqlo,  g_xqlo);
    cudaGetSymbolAddress((void**)&xkhi,  g_xkhi);
    cudaGetSymbolAddress((void**)&xklo,  g_xklo);
    cudaGetSymbolAddress((void**)&xthi,  g_xthi);
    cudaGetSymbolAddress((void**)&xtlo,  g_xtlo);
    cudaGetSymbolAddress((void**)&ctx,   g_ctx);
    cudaGetSymbolAddress((void**)&vothi, g_vothi);
    cudaGetSymbolAddress((void**)&votlo, g_votlo);

    cudaFuncSetAttribute(hmma_gemm<1>, cudaFuncAttributeMaxDynamicSharedMemorySize, HMMA_SMEM);
    cudaFuncSetAttribute(hmma_gemm<3>, cudaFuncAttributeMaxDynamicSharedMemorySize, HMMA_SMEM);
    cudaFuncSetAttribute(hmma_gemm<4>, cudaFuncAttributeMaxDynamicSharedMemorySize, HMMA_SMEM4);
    cudaFuncSetAttribute(hmma_gemm<5>, cudaFuncAttributeMaxDynamicSharedMemorySize, HMMA_SMEM4);

    const int MBT = BB * BT;                  // 4096
    const int HR  = BHEADS * BRANK;           // 1024
    const int HD  = BHEADS * BDIM;            // 16384

    // Input splits
    split_f32<<<(MBT * BDIM / 4 + 255) / 256, 256>>>(x, xhi, xlo, (long long)MBT * BDIM / 4);
    split_f32<<<(HR * BDIM / 4 + 255) / 256, 256>>>(Q, qkhi, qklo, (long long)HR * BDIM / 4);
    split_f32<<<(HR * BDIM / 4 + 255) / 256, 256>>>(K, qkhi + (size_t)HR * BDIM,
                                                    qklo + (size_t)HR * BDIM,
                                                    (long long)HR * BDIM / 4);
    transpose_split<__half><<<dim3(BDIM / 32, BT / 32, BB), dim3(32, 8)>>>(
        x, (long long)BT * BDIM, BT, BDIM, xthi, xtlo, BT, (long long)BDIM * BT);
    transpose_split<__half><<<dim3(BDIM / 32, BDIM / 32, BHEADS), dim3(32, 8)>>>(
        VO, (long long)BDIM * BDIM, BDIM, BDIM, vothi, votlo, HD, (long long)BDIM);

    // 1+2) [xq | xk] = x @ [Q;K]^T -> split (bf16 3-term)
    hmma_gemm<1><<<dim3(2 * HR / HTN, MBT / HTM), 256, HMMA_SMEM>>>(
        xhi, xlo, BDIM, qkhi, qklo, BDIM, nullptr,
        xqhi, xqlo, xkhi, xklo, nullptr, HR, BDIM, 1.0f);
    // 3) E = exp(xq @ xk^T / 32) -> single fp16 + quantized row sums (bf16 3-term)
    hmma_gemm<3><<<dim3(BT / HTN, BT / HTM, BB * BHEADS), 256, BUFSTRIDE>>>(
        xqhi, xqlo, HR, xkhi, xklo, HR, part,
        (__nv_bfloat16*)phi, nullptr, nullptr, nullptr, nullptr, BT, BRANK, 0.03125f);
    // 4) reduce partials -> 1/rowsum
    reduce_inv<<<(BB * BHEADS * BT) / 256, 256>>>(part, rinv);
    // 5) ctx = (E @ x) * rinv  (fp16 2-term) -> single fp16
    hmma_gemm<4><<<dim3(BDIM / HTN, (BB * BHEADS * BT) / HTM), 256, HMMA_SMEM4>>>(
        (const __nv_bfloat16*)phi, nullptr, BT,
        (const __nv_bfloat16*)xthi, (const __nv_bfloat16*)xtlo, BT, nullptr,
        (__nv_bfloat16*)ctx, nullptr, nullptr, nullptr, rinv, 0, BT, 1.0f);
    // 6) out = ctx @ VO  (fp16 2-term)
    hmma_gemm<5><<<dim3(BDIM / HTN, MBT / HTM), 256, HMMA_SMEM4>>>(
        (const __nv_bfloat16*)ctx, nullptr, HD,
        (const __nv_bfloat16*)vothi, (const __nv_bfloat16*)votlo, HD, out,
        nullptr, nullptr, nullptr, nullptr, nullptr, BDIM, HD, 1.0f);
}

// round 11
// speedup vs baseline: 3.6380x; 1.7234x over previous
#include <cuda_runtime.h>
#include <cuda_bf16.h>
#include <cuda_fp16.h>
#include <cstdint>

// Problem constants
#define BDIM   1024
#define BRANK  64
#define BHEADS 16
#define BB     2
#define BT     2048

// ---------------------------------------------------------------------------
// Scratch (device globals)
// ---------------------------------------------------------------------------
__device__ __align__(256) __half g_phi[(size_t)BB * BHEADS * BT * BT];   // E, single fp16
__device__ __align__(256) float g_part[(size_t)BB * BHEADS * BT * 16];
__device__ __align__(256) float g_rinv[(size_t)BB * BHEADS * BT];
__device__ __align__(256) __nv_bfloat16 g_xhi[(size_t)BB * BT * BDIM];
__device__ __align__(256) __nv_bfloat16 g_xlo[(size_t)BB * BT * BDIM];
__device__ __align__(256) __nv_bfloat16 g_qkhi[(size_t)2 * BHEADS * BRANK * BDIM];
__device__ __align__(256) __nv_bfloat16 g_qklo[(size_t)2 * BHEADS * BRANK * BDIM];
__device__ __align__(256) __nv_bfloat16 g_xqhi[(size_t)BB * BT * BHEADS * BRANK];
__device__ __align__(256) __nv_bfloat16 g_xqlo[(size_t)BB * BT * BHEADS * BRANK];
__device__ __align__(256) __nv_bfloat16 g_xkhi[(size_t)BB * BT * BHEADS * BRANK];
__device__ __align__(256) __nv_bfloat16 g_xklo[(size_t)BB * BT * BHEADS * BRANK];
__device__ __align__(256) __half g_xt[(size_t)BB * BDIM * BT];           // xT single fp16
__device__ __align__(256) __half g_ctx[(size_t)BB * BT * BHEADS * BDIM]; // ctx single fp16
__device__ __align__(256) __half g_vot[(size_t)BDIM * BHEADS * BDIM];    // VOT single fp16

// ---------------------------------------------------------------------------
// Helpers
// ---------------------------------------------------------------------------
__device__ __forceinline__ uint32_t smem_u32(const void* p) {
    return (uint32_t)__cvta_generic_to_shared(p);
}

#define CP16(s, g) asm volatile("cp.async.cg.shared.global [%0], [%1], 16;" :: "r"(s), "l"(g))

__device__ __forceinline__ void ldsm4(uint32_t* r, uint32_t addr) {
    asm volatile("ldmatrix.sync.aligned.m8n8.x4.shared.b16 {%0,%1,%2,%3}, [%4];"
        : "=r"(r[0]), "=r"(r[1]), "=r"(r[2]), "=r"(r[3]) : "r"(addr));
}

__device__ __forceinline__ void mma16816(float* c, const uint32_t* a, const uint32_t* b) {
    asm volatile("mma.sync.aligned.m16n8k16.row.col.f32.bf16.bf16.f32 "
        "{%0,%1,%2,%3}, {%4,%5,%6,%7}, {%8,%9}, {%0,%1,%2,%3};"
        : "+f"(c[0]), "+f"(c[1]), "+f"(c[2]), "+f"(c[3])
        : "r"(a[0]), "r"(a[1]), "r"(a[2]), "r"(a[3]), "r"(b[0]), "r"(b[1]));
}

__device__ __forceinline__ void mma16816h(float* c, const uint32_t* a, const uint32_t* b) {
    asm volatile("mma.sync.aligned.m16n8k16.row.col.f32.f16.f16.f32 "
        "{%0,%1,%2,%3}, {%4,%5,%6,%7}, {%8,%9}, {%0,%1,%2,%3};"
        : "+f"(c[0]), "+f"(c[1]), "+f"(c[2]), "+f"(c[3])
        : "r"(a[0]), "r"(a[1]), "r"(a[2]), "r"(a[3]), "r"(b[0]), "r"(b[1]));
}

template <int N>
__device__ __forceinline__ void cp_wait() {
    asm volatile("cp.async.wait_group %0;" :: "n"(N) : "memory");
}

// ---------------------------------------------------------------------------
// Elementwise bf16 hi/lo split
// ---------------------------------------------------------------------------
__global__ __launch_bounds__(256)
void split_f32(const float* __restrict__ in,
               __nv_bfloat16* __restrict__ oh, __nv_bfloat16* __restrict__ ol,
               long long n4)
{
    const long long i = (long long)blockIdx.x * 256 + threadIdx.x;
    if (i >= n4) return;
    float4 v = reinterpret_cast<const float4*>(in)[i];
    __nv_bfloat162 h01, h23, l01, l23;
    h01.x = __float2bfloat16(v.x); h01.y = __float2bfloat16(v.y);
    h23.x = __float2bfloat16(v.z); h23.y = __float2bfloat16(v.w);
    l01.x = __float2bfloat16(v.x - __bfloat162float(h01.x));
    l01.y = __float2bfloat16(v.y - __bfloat162float(h01.y));
    l23.x = __float2bfloat16(v.z - __bfloat162float(h23.x));
    l23.y = __float2bfloat16(v.w - __bfloat162float(h23.y));
    reinterpret_cast<__nv_bfloat162*>(oh)[2 * i + 0] = h01;
    reinterpret_cast<__nv_bfloat162*>(oh)[2 * i + 1] = h23;
    reinterpret_cast<__nv_bfloat162*>(ol)[2 * i + 0] = l01;
    reinterpret_cast<__nv_bfloat162*>(ol)[2 * i + 1] = l23;
}

// ---------------------------------------------------------------------------
// Transpose to single fp16: out[c][r] = (half)in[r][c], batched over z
// ---------------------------------------------------------------------------
__global__ __launch_bounds__(256)
void transpose_h(const float* __restrict__ in, long long inBS, int R, int C,
                 __half* __restrict__ oh, int oLd, long long oBS)
{
    __shared__ float tile[32][33];
    const int z = blockIdx.z;
    const float* ip = in + (long long)z * inBS;
    const int c0 = blockIdx.x * 32;
    const int r0 = blockIdx.y * 32;
    const int tx = threadIdx.x;
    const int ty = threadIdx.y;

#pragma unroll
    for (int i = 0; i < 32; i += 8)
        tile[ty + i][tx] = ip[(long long)(r0 + ty + i) * C + c0 + tx];
    __syncthreads();

    const long long ob = (long long)z * oBS;
#pragma unroll
    for (int i = 0; i < 32; i += 8) {
        float v = tile[tx][ty + i];
        long long o = ob + (long long)(c0 + ty + i) * oLd + r0 + tx;
        oh[o] = __float2half(v);
    }
}

// ---------------------------------------------------------------------------
// Reduce 16 per-row partials -> 1/rowsum
// ---------------------------------------------------------------------------
__global__ __launch_bounds__(256)
void reduce_inv(const float* __restrict__ part, float* __restrict__ inv)
{
    const long long r = (long long)blockIdx.x * 256 + threadIdx.x;
    const float4* p = reinterpret_cast<const float4*>(part + r * 16);
    float4 a = p[0], b = p[1], c = p[2], d = p[3];
    float s = ((a.x + a.y) + (a.z + a.w)) + ((b.x + b.y) + (b.z + b.w))
            + ((c.x + c.y) + (c.z + c.w)) + ((d.x + d.y) + (d.z + d.w));
    inv[r] = 1.0f / s;
}

// ---------------------------------------------------------------------------
// HMMA GEMM, 3-stage cp.async pipeline, 128x128 tile, KC=64.
// STAGE==1: bf16 3-term; epilogue hi/lo split; ncol<1024 -> xq else xk.
// STAGE==3: bf16 3-term; z=(b,h); epilogue exp -> single fp16 E + row sums
//           of the QUANTIZED fp16 values.
// STAGE==4: fp16 1-term (E*X); epilogue *= Rinv, ctx single fp16 scatter.
// STAGE==5: fp16 1-term (ctx*V); epilogue fp32.
// ---------------------------------------------------------------------------
#define HTM 128
#define HTN 128
#define HTK 64

#define BUFSTRIDE   65536   // 4 tiles (bf16 3-term)
#define BUFSTRIDE1  32768   // 2 tiles (fp16 1-term)
#define HMMA_SMEM   (3 * BUFSTRIDE)    // 192 KB
#define HMMA_SMEM1  (3 * BUFSTRIDE1)   // 96 KB

template <int STAGE>
__global__ __launch_bounds__(256, (STAGE >= 3) ? 2 : 1)
void hmma_gemm(const __nv_bfloat16* __restrict__ Ahi, const __nv_bfloat16* __restrict__ Alo,
               int lda,
               const __nv_bfloat16* __restrict__ Bhi, const __nv_bfloat16* __restrict__ Blo,
               int ldb,
               float* __restrict__ Cf,
               __nv_bfloat16* __restrict__ Chi, __nv_bfloat16* __restrict__ Clo,
               __nv_bfloat16* __restrict__ Chi2, __nv_bfloat16* __restrict__ Clo2,
               const float* __restrict__ Rinv,
               int ldc, int K, float alpha)
{
    extern __shared__ char smem[];
    __shared__ float srow[2][HTM];
    const uint32_t sb = smem_u32(smem);
    const int tid  = threadIdx.x;
    const int wid  = tid >> 5;
    const int lane = tid & 31;
    const int mw = wid & 3;
    const int nw = wid >> 2;

    constexpr bool ONETERM = (STAGE >= 4);
    constexpr uint32_t STRIDE = ONETERM ? BUFSTRIDE1 : BUFSTRIDE;
    constexpr uint32_t ALO_O  = 16384;
    constexpr uint32_t BHI_O  = ONETERM ? 16384 : 32768;
    constexpr uint32_t BLO_O  = 49152;

    const long long m0 = (long long)blockIdx.y * HTM;
    const int n0 = blockIdx.x * HTN;

    const __nv_bfloat16 *Abh, *Abl, *Bbh, *Bbl;
    if (STAGE == 3) {
        const int z = blockIdx.z;
        const int b = z >> 4;
        const int h = z & 15;
        const long long ao = ((long long)b * BT + m0) * lda + h * BRANK;
        const long long bo = ((long long)b * BT + n0) * ldb + h * BRANK;
        Abh = Ahi + ao;  Abl = Alo + ao;
        Bbh = Bhi + bo;  Bbl = Blo + bo;
    } else if (STAGE == 4) {
        const long long b = m0 >> 15;
        Abh = Ahi + m0 * lda;  Abl = nullptr;
        Bbh = Bhi + b * ((long long)BDIM * BT) + (long long)n0 * ldb;
        Bbl = nullptr;
    } else if (STAGE == 5) {
        Abh = Ahi + m0 * lda;  Abl = nullptr;
        Bbh = Bhi + (long long)n0 * ldb;  Bbl = nullptr;
    } else {
        Abh = Ahi + m0 * lda;  Abl = Alo + m0 * lda;
        Bbh = Bhi + (long long)n0 * ldb;  Bbl = Blo + (long long)n0 * ldb;
    }

    float acc[2][8][4];
#pragma unroll
    for (int i = 0; i < 2; i++)
#pragma unroll
        for (int f = 0; f < 8; f++)
#pragma unroll
            for (int e = 0; e < 4; e++) acc[i][f][e] = 0.0f;

    const int NC = K / HTK;

    auto load_chunk = [&](int c, int buf) {
        const long long kg = (long long)c * HTK;
        const uint32_t bb = sb + buf * STRIDE;
#pragma unroll
        for (int i = 0; i < 4; i++) {
            const int idx = tid + i * 256;
            const int r  = idx >> 3;
            const int ck = idx & 7;
            const uint32_t so = (uint32_t)(r * 128 + ((ck ^ (r & 7)) << 4));
            const long long ga = (long long)r * lda + kg + ck * 8;
            const long long gb = (long long)r * ldb + kg + ck * 8;
            CP16(bb + so, (const void*)(Abh + ga));
            if (!ONETERM) CP16(bb + ALO_O + so, (const void*)(Abl + ga));
            CP16(bb + BHI_O + so, (const void*)(Bbh + gb));
            if (!ONETERM) CP16(bb + BLO_O + so, (const void*)(Bbl + gb));
        }
        asm volatile("cp.async.commit_group;" ::: "memory");
    };

    load_chunk(0, 0);
    if (NC > 1) load_chunk(1, 1);

    for (int c = 0; c < NC; c++) {
        if (c + 2 < NC) load_chunk(c + 2, (c + 2) % 3);
        const int pend = (NC - 1 - c >= 2) ? 2 : (NC - 1 - c);
        if (pend == 2)      cp_wait<2>();
        else if (pend == 1) cp_wait<1>();
        else                cp_wait<0>();
        __syncthreads();

        const uint32_t ab = sb + (c % 3) * STRIDE;
#pragma unroll
        for (int ks = 0; ks < 4; ks++) {
            uint32_t ah[2][4], al[2][4], bh[4][4], bl[4][4];
#pragma unroll
            for (int i = 0; i < 2; i++) {
                const int r  = mw * 32 + i * 16 + (lane & 15);
                const int ck = ks * 2 + (lane >> 4);
                const uint32_t off = (uint32_t)(r * 128 + ((ck ^ (r & 7)) << 4));
                ldsm4(ah[i], ab + off);
                if (!ONETERM) ldsm4(al[i], ab + ALO_O + off);
            }
#pragma unroll
            for (int j = 0; j < 4; j++) {
                const int r  = nw * 64 + j * 16 + (lane & 7) + ((lane >> 4) & 1) * 8;
                const int ck = ks * 2 + ((lane >> 3) & 1);
                const uint32_t off = (uint32_t)(r * 128 + ((ck ^ (r & 7)) << 4));
                ldsm4(bh[j], ab + BHI_O + off);
                if (!ONETERM) ldsm4(bl[j], ab + BLO_O + off);
            }
#pragma unroll
            for (int i = 0; i < 2; i++)
#pragma unroll
                for (int f = 0; f < 8; f++) {
                    const uint32_t* Bh = &bh[f >> 1][(f & 1) * 2];
                    if (ONETERM) {
                        mma16816h(acc[i][f], ah[i], Bh);
                    } else {
                        const uint32_t* Bl = &bl[f >> 1][(f & 1) * 2];
                        mma16816(acc[i][f], ah[i], Bh);
                        mma16816(acc[i][f], ah[i], Bl);
                        mma16816(acc[i][f], al[i], Bh);
                    }
                }
        }
        __syncthreads();
    }

    // Epilogue
#pragma unroll
    for (int i = 0; i < 2; i++) {
#pragma unroll
        for (int hr = 0; hr < 2; hr++) {
            const long long mg = m0 + mw * 32 + i * 16 + hr * 8 + (lane >> 2);
            const int ncol = n0 + nw * 64 + (lane & 3) * 2;
            if (STAGE == 5) {
                float* dst = Cf + mg * ldc + ncol;
#pragma unroll
                for (int f = 0; f < 8; f++) {
                    float2 v;
                    v.x = acc[i][f][hr * 2 + 0];
                    v.y = acc[i][f][hr * 2 + 1];
                    *reinterpret_cast<float2*>(dst + f * 8) = v;
                }
            } else if (STAGE == 3) {
                // E = exp(score) -> single fp16; rowsum of QUANTIZED values
                const long long orow = (long long)blockIdx.z * BT * BT + mg * ldc + ncol;
                float part = 0.0f;
#pragma unroll
                for (int f = 0; f < 8; f++) {
                    const float e0 = __expf(acc[i][f][hr * 2 + 0] * alpha);
                    const float e1 = __expf(acc[i][f][hr * 2 + 1] * alpha);
                    __half2 hv;
                    hv.x = __float2half(e0);
                    hv.y = __float2half(e1);
                    part += __half2float(hv.x) + __half2float(hv.y);
                    *reinterpret_cast<__half2*>(
                        reinterpret_cast<__half*>(Chi) + orow + f * 8) = hv;
                }
                part += __shfl_xor_sync(0xffffffffu, part, 1);
                part += __shfl_xor_sync(0xffffffffu, part, 2);
                if ((lane & 3) == 0)
                    srow[nw][mw * 32 + i * 16 + hr * 8 + (lane >> 2)] = part;
            } else if (STAGE == 1) {
                const bool isK = (ncol >= 1024);
                __nv_bfloat16* DH = isK ? Chi2 : Chi;
                __nv_bfloat16* DL = isK ? Clo2 : Clo;
                const long long orow = mg * ldc + (ncol - (isK ? 1024 : 0));
#pragma unroll
                for (int f = 0; f < 8; f++) {
                    const float v0 = acc[i][f][hr * 2 + 0];
                    const float v1 = acc[i][f][hr * 2 + 1];
                    __nv_bfloat162 hv, lv;
                    hv.x = __float2bfloat16(v0);
                    hv.y = __float2bfloat16(v1);
                    lv.x = __float2bfloat16(v0 - __bfloat162float(hv.x));
                    lv.y = __float2bfloat16(v1 - __bfloat162float(hv.y));
                    *reinterpret_cast<__nv_bfloat162*>(DH + orow + f * 8) = hv;
                    *reinterpret_cast<__nv_bfloat162*>(DL + orow + f * 8) = lv;
                }
            } else { // STAGE == 4 : ctx single fp16
                const float rs = Rinv[mg];
                const int b = (int)(mg >> 15);
                const int h = (int)((mg >> 11) & 15);
                const int t = (int)(mg & 2047);
                const long long orow =
                    ((long long)b * BT + t) * ((long long)BHEADS * BDIM) +
                    (long long)h * BDIM + ncol;
                __half* dst = reinterpret_cast<__half*>(Chi);
#pragma unroll
                for (int f = 0; f < 8; f++) {
                    __half2 hv;
                    hv.x = __float2half(acc[i][f][hr * 2 + 0] * rs);
                    hv.y = __float2half(acc[i][f][hr * 2 + 1] * rs);
                    *reinterpret_cast<__half2*>(dst + orow + f * 8) = hv;
                }
            }
        }
    }

    if (STAGE == 3) {
        __syncthreads();
        if (tid < HTM) {
            const float s = srow[0][tid] + srow[1][tid];
            Cf[((long long)blockIdx.z * BT + m0 + tid) * 16 + blockIdx.x] = s;
        }
    }
}

// ---------------------------------------------------------------------------
// Launch
// ---------------------------------------------------------------------------
extern "C" void kernel_launch(void* const* d_in, const int* in_sizes, int n_in,
                              void* d_out, int out_size)
{
    const float* x  = (const float*)d_in[0];
    const float* Q  = (const float*)d_in[1];
    const float* K  = (const float*)d_in[2];
    const float* VO = (const float*)d_in[3];
    float* out = (float*)d_out;

    float *part, *rinv;
    __half *phi, *xt, *ctx, *vot;
    __nv_bfloat16 *xhi, *xlo, *qkhi, *qklo;
    __nv_bfloat16 *xqhi, *xqlo, *xkhi, *xklo;
    cudaGetSymbolAddress((void**)&part,  g_part);
    cudaGetSymbolAddress((void**)&rinv,  g_rinv);
    cudaGetSymbolAddress((void**)&phi,   g_phi);
    cudaGetSymbolAddress((void**)&xhi,   g_xhi);
    cudaGetSymbolAddress((void**)&xlo,   g_xlo);
    cudaGetSymbolAddress((void**)&qkhi,  g_qkhi);
    cudaGetSymbolAddress((void**)&qklo,  g_qklo);
    cudaGetSymbolAddress((void**)&xqhi,  g_xqhi);
    cudaGetSymbolAddress((void**)&xqlo,  g_xqlo);
    cudaGetSymbolAddress((void**)&xkhi,  g_xkhi);
    cudaGetSymbolAddress((void**)&xklo,  g_xklo);
    cudaGetSymbolAddress((void**)&xt,    g_xt);
    cudaGetSymbolAddress((void**)&ctx,   g_ctx);
    cudaGetSymbolAddress((void**)&vot,   g_vot);

    cudaFuncSetAttribute(hmma_gemm<1>, cudaFuncAttributeMaxDynamicSharedMemorySize, HMMA_SMEM);
    cudaFuncSetAttribute(hmma_gemm<3>, cudaFuncAttributeMaxDynamicSharedMemorySize, HMMA_SMEM);
    cudaFuncSetAttribute(hmma_gemm<4>, cudaFuncAttributeMaxDynamicSharedMemorySize, HMMA_SMEM1);
    cudaFuncSetAttribute(hmma_gemm<5>, cudaFuncAttributeMaxDynamicSharedMemorySize, HMMA_SMEM1);

    const int MBT = BB * BT;                  // 4096
    const int HR  = BHEADS * BRANK;           // 1024
    const int HD  = BHEADS * BDIM;            // 16384

    // Input splits
    split_f32<<<(MBT * BDIM / 4 + 255) / 256, 256>>>(x, xhi, xlo, (long long)MBT * BDIM / 4);
    split_f32<<<(HR * BDIM / 4 + 255) / 256, 256>>>(Q, qkhi, qklo, (long long)HR * BDIM / 4);
    split_f32<<<(HR * BDIM / 4 + 255) / 256, 256>>>(K, qkhi + (size_t)HR * BDIM,
                                                    qklo + (size_t)HR * BDIM,
                                                    (long long)HR * BDIM / 4);
    transpose_h<<<dim3(BDIM / 32, BT / 32, BB), dim3(32, 8)>>>(
        x, (long long)BT * BDIM, BT, BDIM, xt, BT, (long long)BDIM * BT);
    transpose_h<<<dim3(BDIM / 32, BDIM / 32, BHEADS), dim3(32, 8)>>>(
        VO, (long long)BDIM * BDIM, BDIM, BDIM, vot, HD, (long long)BDIM);

    // 1+2) [xq | xk] = x @ [Q;K]^T -> split (bf16 3-term)
    hmma_gemm<1><<<dim3(2 * HR / HTN, MBT / HTM), 256, HMMA_SMEM>>>(
        xhi, xlo, BDIM, qkhi, qklo, BDIM, nullptr,
        xqhi, xqlo, xkhi, xklo, nullptr, HR, BDIM, 1.0f);
    // 3) E = exp(xq @ xk^T / 32) -> single fp16 + quantized row sums (bf16 3-term)
    hmma_gemm<3><<<dim3(BT / HTN, BT / HTM, BB * BHEADS), 256, BUFSTRIDE>>>(
        xqhi, xqlo, HR, xkhi, xklo, HR, part,
        (__nv_bfloat16*)phi, nullptr, nullptr, nullptr, nullptr, BT, BRANK, 0.03125f);
    // 4) reduce partials -> 1/rowsum
    reduce_inv<<<(BB * BHEADS * BT) / 256, 256>>>(part, rinv);
    // 5) ctx = (E @ x) * rinv  (fp16 1-term) -> single fp16
    hmma_gemm<4><<<dim3(BDIM / HTN, (BB * BHEADS * BT) / HTM), 256, HMMA_SMEM1>>>(
        (const __nv_bfloat16*)phi, nullptr, BT,
        (const __nv_bfloat16*)xt, nullptr, BT, nullptr,
        (__nv_bfloat16*)ctx, nullptr, nullptr, nullptr, rinv, 0, BT, 1.0f);
    // 6) out = ctx @ VO  (fp16 1-term)
    hmma_gemm<5><<<dim3(BDIM / HTN, MBT / HTM), 256, HMMA_SMEM1>>>(
        (const __nv_bfloat16*)ctx, nullptr, HD,
        (const __nv_bfloat16*)vot, nullptr, HD, out,
        nullptr, nullptr, nullptr, nullptr, nullptr, BDIM, HD, 1.0f);
}

// round 12
// speedup vs baseline: 4.0923x; 1.1249x over previous
#include <cuda_runtime.h>
#include <cuda_fp16.h>
#include <cstdint>

// Problem constants
#define BDIM   1024
#define BRANK  64
#define BHEADS 16
#define BB     2
#define BT     2048

// ---------------------------------------------------------------------------
// Scratch (device globals) — all operands single fp16
// ---------------------------------------------------------------------------
__device__ __align__(256) __half g_e[(size_t)BB * BHEADS * BT * BT];     // E = exp(scores)
__device__ __align__(256) float g_part[(size_t)BB * BHEADS * BT * 16];
__device__ __align__(256) float g_rinv[(size_t)BB * BHEADS * BT];
__device__ __align__(256) __half g_xh[(size_t)BB * BT * BDIM];           // x row-major
__device__ __align__(256) __half g_qkh[(size_t)2 * BHEADS * BRANK * BDIM]; // [Q;K] stacked
__device__ __align__(256) __half g_xq[(size_t)BB * BT * BHEADS * BRANK];
__device__ __align__(256) __half g_xk[(size_t)BB * BT * BHEADS * BRANK];
__device__ __align__(256) __half g_xt[(size_t)BB * BDIM * BT];           // x^T per batch
__device__ __align__(256) __half g_ctx[(size_t)BB * BT * BHEADS * BDIM];
__device__ __align__(256) __half g_vot[(size_t)BDIM * BHEADS * BDIM];    // VO^T

// ---------------------------------------------------------------------------
// Helpers
// ---------------------------------------------------------------------------
__device__ __forceinline__ uint32_t smem_u32(const void* p) {
    return (uint32_t)__cvta_generic_to_shared(p);
}

#define CP16(s, g) asm volatile("cp.async.cg.shared.global [%0], [%1], 16;" :: "r"(s), "l"(g))

__device__ __forceinline__ void ldsm4(uint32_t* r, uint32_t addr) {
    asm volatile("ldmatrix.sync.aligned.m8n8.x4.shared.b16 {%0,%1,%2,%3}, [%4];"
        : "=r"(r[0]), "=r"(r[1]), "=r"(r[2]), "=r"(r[3]) : "r"(addr));
}

__device__ __forceinline__ void mma16816h(float* c, const uint32_t* a, const uint32_t* b) {
    asm volatile("mma.sync.aligned.m16n8k16.row.col.f32.f16.f16.f32 "
        "{%0,%1,%2,%3}, {%4,%5,%6,%7}, {%8,%9}, {%0,%1,%2,%3};"
        : "+f"(c[0]), "+f"(c[1]), "+f"(c[2]), "+f"(c[3])
        : "r"(a[0]), "r"(a[1]), "r"(a[2]), "r"(a[3]), "r"(b[0]), "r"(b[1]));
}

template <int N>
__device__ __forceinline__ void cp_wait() {
    asm volatile("cp.async.wait_group %0;" :: "n"(N) : "memory");
}

// ---------------------------------------------------------------------------
// Elementwise fp32 -> fp16 convert (float4 per thread)
// ---------------------------------------------------------------------------
__global__ __launch_bounds__(256)
void convert_h(const float* __restrict__ in, __half* __restrict__ oh, long long n4)
{
    const long long i = (long long)blockIdx.x * 256 + threadIdx.x;
    if (i >= n4) return;
    float4 v = reinterpret_cast<const float4*>(in)[i];
    __half2 h01, h23;
    h01.x = __float2half(v.x); h01.y = __float2half(v.y);
    h23.x = __float2half(v.z); h23.y = __float2half(v.w);
    reinterpret_cast<__half2*>(oh)[2 * i + 0] = h01;
    reinterpret_cast<__half2*>(oh)[2 * i + 1] = h23;
}

// ---------------------------------------------------------------------------
// Transpose to fp16: out[c][r] = (half)in[r][c], batched over z
// ---------------------------------------------------------------------------
__global__ __launch_bounds__(256)
void transpose_h(const float* __restrict__ in, long long inBS, int R, int C,
                 __half* __restrict__ oh, int oLd, long long oBS)
{
    __shared__ float tile[32][33];
    const int z = blockIdx.z;
    const float* ip = in + (long long)z * inBS;
    const int c0 = blockIdx.x * 32;
    const int r0 = blockIdx.y * 32;
    const int tx = threadIdx.x;
    const int ty = threadIdx.y;

#pragma unroll
    for (int i = 0; i < 32; i += 8)
        tile[ty + i][tx] = ip[(long long)(r0 + ty + i) * C + c0 + tx];
    __syncthreads();

    const long long ob = (long long)z * oBS;
#pragma unroll
    for (int i = 0; i < 32; i += 8) {
        float v = tile[tx][ty + i];
        long long o = ob + (long long)(c0 + ty + i) * oLd + r0 + tx;
        oh[o] = __float2half(v);
    }
}

// ---------------------------------------------------------------------------
// Reduce 16 per-row partials -> 1/rowsum
// ---------------------------------------------------------------------------
__global__ __launch_bounds__(256)
void reduce_inv(const float* __restrict__ part, float* __restrict__ inv)
{
    const long long r = (long long)blockIdx.x * 256 + threadIdx.x;
    const float4* p = reinterpret_cast<const float4*>(part + r * 16);
    float4 a = p[0], b = p[1], c = p[2], d = p[3];
    float s = ((a.x + a.y) + (a.z + a.w)) + ((b.x + b.y) + (b.z + b.w))
            + ((c.x + c.y) + (c.z + c.w)) + ((d.x + d.y) + (d.z + d.w));
    inv[r] = 1.0f / s;
}

// ---------------------------------------------------------------------------
// fp16 1-term HMMA GEMM, 3-stage cp.async pipeline, 128x128 tile, KC=64.
// C = A @ B^T, fp32 accumulate. A: [M][K] rows (lda), B: [N][K] rows (ldb).
// STAGE==1: epilogue fp16; ncol<1024 -> C1=xq else C2=xk (ldc).
// STAGE==3: z=(b,h); epilogue exp(acc*alpha) -> fp16 E + quantized row sums.
// STAGE==4: A=E flat; B=xT per batch; epilogue *= Rinv[row], fp16 ctx scatter.
// STAGE==5: epilogue fp32 -> Cf.
// ---------------------------------------------------------------------------
#define HTM 128
#define HTN 128
#define HTK 64

#define BUFSTRIDE 32768              // 2 tiles x 16KB
#define BHI_O 16384
#define HMMA_SMEM (3 * BUFSTRIDE)    // 96 KB

template <int STAGE>
__global__ __launch_bounds__(256, 2)
void hmma_gemm(const __half* __restrict__ A, int lda,
               const __half* __restrict__ B, int ldb,
               float* __restrict__ Cf,
               __half* __restrict__ C1, __half* __restrict__ C2,
               const float* __restrict__ Rinv,
               int ldc, int K, float alpha)
{
    extern __shared__ char smem[];
    __shared__ float srow[2][HTM];
    const uint32_t sb = smem_u32(smem);
    const int tid  = threadIdx.x;
    const int wid  = tid >> 5;
    const int lane = tid & 31;
    const int mw = wid & 3;
    const int nw = wid >> 2;

    const long long m0 = (long long)blockIdx.y * HTM;
    const int n0 = blockIdx.x * HTN;

    const __half *Ab, *Bb;
    if (STAGE == 3) {
        const int z = blockIdx.z;
        const int b = z >> 4;
        const int h = z & 15;
        Ab = A + ((long long)b * BT + m0) * lda + h * BRANK;
        Bb = B + ((long long)b * BT + n0) * ldb + h * BRANK;
    } else if (STAGE == 4) {
        const long long b = m0 >> 15;       // 32768 flat rows per batch
        Ab = A + m0 * lda;
        Bb = B + b * ((long long)BDIM * BT) + (long long)n0 * ldb;
    } else {
        Ab = A + m0 * lda;
        Bb = B + (long long)n0 * ldb;
    }

    float acc[2][8][4];
#pragma unroll
    for (int i = 0; i < 2; i++)
#pragma unroll
        for (int f = 0; f < 8; f++)
#pragma unroll
            for (int e = 0; e < 4; e++) acc[i][f][e] = 0.0f;

    const int NC = K / HTK;

    auto load_chunk = [&](int c, int buf) {
        const long long kg = (long long)c * HTK;
        const uint32_t bb = sb + buf * BUFSTRIDE;
#pragma unroll
        for (int i = 0; i < 4; i++) {
            const int idx = tid + i * 256;
            const int r  = idx >> 3;
            const int ck = idx & 7;
            const uint32_t so = (uint32_t)(r * 128 + ((ck ^ (r & 7)) << 4));
            const long long ga = (long long)r * lda + kg + ck * 8;
            const long long gb = (long long)r * ldb + kg + ck * 8;
            CP16(bb + so, (const void*)(Ab + ga));
            CP16(bb + BHI_O + so, (const void*)(Bb + gb));
        }
        asm volatile("cp.async.commit_group;" ::: "memory");
    };

    load_chunk(0, 0);
    if (NC > 1) load_chunk(1, 1);

    for (int c = 0; c < NC; c++) {
        if (c + 2 < NC) load_chunk(c + 2, (c + 2) % 3);
        const int pend = (NC - 1 - c >= 2) ? 2 : (NC - 1 - c);
        if (pend == 2)      cp_wait<2>();
        else if (pend == 1) cp_wait<1>();
        else                cp_wait<0>();
        __syncthreads();

        const uint32_t ab = sb + (c % 3) * BUFSTRIDE;
#pragma unroll
        for (int ks = 0; ks < 4; ks++) {
            uint32_t ah[2][4], bh[4][4];
#pragma unroll
            for (int i = 0; i < 2; i++) {
                const int r  = mw * 32 + i * 16 + (lane & 15);
                const int ck = ks * 2 + (lane >> 4);
                const uint32_t off = (uint32_t)(r * 128 + ((ck ^ (r & 7)) << 4));
                ldsm4(ah[i], ab + off);
            }
#pragma unroll
            for (int j = 0; j < 4; j++) {
                const int r  = nw * 64 + j * 16 + (lane & 7) + ((lane >> 4) & 1) * 8;
                const int ck = ks * 2 + ((lane >> 3) & 1);
                const uint32_t off = (uint32_t)(r * 128 + ((ck ^ (r & 7)) << 4));
                ldsm4(bh[j], ab + BHI_O + off);
            }
#pragma unroll
            for (int i = 0; i < 2; i++)
#pragma unroll
                for (int f = 0; f < 8; f++)
                    mma16816h(acc[i][f], ah[i], &bh[f >> 1][(f & 1) * 2]);
        }
        __syncthreads();
    }

    // Epilogue
#pragma unroll
    for (int i = 0; i < 2; i++) {
#pragma unroll
        for (int hr = 0; hr < 2; hr++) {
            const long long mg = m0 + mw * 32 + i * 16 + hr * 8 + (lane >> 2);
            const int ncol = n0 + nw * 64 + (lane & 3) * 2;
            if (STAGE == 5) {
                float* dst = Cf + mg * ldc + ncol;
#pragma unroll
                for (int f = 0; f < 8; f++) {
                    float2 v;
                    v.x = acc[i][f][hr * 2 + 0];
                    v.y = acc[i][f][hr * 2 + 1];
                    *reinterpret_cast<float2*>(dst + f * 8) = v;
                }
            } else if (STAGE == 3) {
                // E = exp(score) -> fp16; rowsum of QUANTIZED values
                const long long orow = (long long)blockIdx.z * BT * BT + mg * ldc + ncol;
                float part = 0.0f;
#pragma unroll
                for (int f = 0; f < 8; f++) {
                    const float e0 = __expf(acc[i][f][hr * 2 + 0] * alpha);
                    const float e1 = __expf(acc[i][f][hr * 2 + 1] * alpha);
                    __half2 hv;
                    hv.x = __float2half(e0);
                    hv.y = __float2half(e1);
                    part += __half2float(hv.x) + __half2float(hv.y);
                    *reinterpret_cast<__half2*>(C1 + orow + f * 8) = hv;
                }
                part += __shfl_xor_sync(0xffffffffu, part, 1);
                part += __shfl_xor_sync(0xffffffffu, part, 2);
                if ((lane & 3) == 0)
                    srow[nw][mw * 32 + i * 16 + hr * 8 + (lane >> 2)] = part;
            } else if (STAGE == 1) {
                const bool isK = (ncol >= 1024);
                __half* D = isK ? C2 : C1;
                const long long orow = mg * ldc + (ncol - (isK ? 1024 : 0));
#pragma unroll
                for (int f = 0; f < 8; f++) {
                    __half2 hv;
                    hv.x = __float2half(acc[i][f][hr * 2 + 0]);
                    hv.y = __float2half(acc[i][f][hr * 2 + 1]);
                    *reinterpret_cast<__half2*>(D + orow + f * 8) = hv;
                }
            } else { // STAGE == 4 : ctx fp16 scatter
                const float rs = Rinv[mg];
                const int b = (int)(mg >> 15);
                const int h = (int)((mg >> 11) & 15);
                const int t = (int)(mg & 2047);
                const long long orow =
                    ((long long)b * BT + t) * ((long long)BHEADS * BDIM) +
                    (long long)h * BDIM + ncol;
#pragma unroll
                for (int f = 0; f < 8; f++) {
                    __half2 hv;
                    hv.x = __float2half(acc[i][f][hr * 2 + 0] * rs);
                    hv.y = __float2half(acc[i][f][hr * 2 + 1] * rs);
                    *reinterpret_cast<__half2*>(C1 + orow + f * 8) = hv;
                }
            }
        }
    }

    if (STAGE == 3) {
        __syncthreads();
        if (tid < HTM) {
            const float s = srow[0][tid] + srow[1][tid];
            Cf[((long long)blockIdx.z * BT + m0 + tid) * 16 + blockIdx.x] = s;
        }
    }
}

// ---------------------------------------------------------------------------
// Launch
// ---------------------------------------------------------------------------
extern "C" void kernel_launch(void* const* d_in, const int* in_sizes, int n_in,
                              void* d_out, int out_size)
{
    const float* x  = (const float*)d_in[0];
    const float* Q  = (const float*)d_in[1];
    const float* K  = (const float*)d_in[2];
    const float* VO = (const float*)d_in[3];
    float* out = (float*)d_out;

    float *part, *rinv;
    __half *e, *xh, *qkh, *xq, *xk, *xt, *ctx, *vot;
    cudaGetSymbolAddress((void**)&part, g_part);
    cudaGetSymbolAddress((void**)&rinv, g_rinv);
    cudaGetSymbolAddress((void**)&e,    g_e);
    cudaGetSymbolAddress((void**)&xh,   g_xh);
    cudaGetSymbolAddress((void**)&qkh,  g_qkh);
    cudaGetSymbolAddress((void**)&xq,   g_xq);
    cudaGetSymbolAddress((void**)&xk,   g_xk);
    cudaGetSymbolAddress((void**)&xt,   g_xt);
    cudaGetSymbolAddress((void**)&ctx,  g_ctx);
    cudaGetSymbolAddress((void**)&vot,  g_vot);

    cudaFuncSetAttribute(hmma_gemm<1>, cudaFuncAttributeMaxDynamicSharedMemorySize, HMMA_SMEM);
    cudaFuncSetAttribute(hmma_gemm<3>, cudaFuncAttributeMaxDynamicSharedMemorySize, HMMA_SMEM);
    cudaFuncSetAttribute(hmma_gemm<4>, cudaFuncAttributeMaxDynamicSharedMemorySize, HMMA_SMEM);
    cudaFuncSetAttribute(hmma_gemm<5>, cudaFuncAttributeMaxDynamicSharedMemorySize, HMMA_SMEM);

    const int MBT = BB * BT;                  // 4096
    const int HR  = BHEADS * BRANK;           // 1024
    const int HD  = BHEADS * BDIM;            // 16384

    // fp16 conversions / transposes
    convert_h<<<MBT * BDIM / 4 / 256, 256>>>(x, xh, (long long)MBT * BDIM / 4);
    convert_h<<<HR * BDIM / 4 / 256, 256>>>(Q, qkh, (long long)HR * BDIM / 4);
    convert_h<<<HR * BDIM / 4 / 256, 256>>>(K, qkh + (size_t)HR * BDIM, (long long)HR * BDIM / 4);
    transpose_h<<<dim3(BDIM / 32, BT / 32, BB), dim3(32, 8)>>>(
        x, (long long)BT * BDIM, BT, BDIM, xt, BT, (long long)BDIM * BT);
    transpose_h<<<dim3(BDIM / 32, BDIM / 32, BHEADS), dim3(32, 8)>>>(
        VO, (long long)BDIM * BDIM, BDIM, BDIM, vot, HD, (long long)BDIM);

    // 1+2) [xq | xk] = x @ [Q;K]^T   M=4096, N=2048, K=1024
    hmma_gemm<1><<<dim3(2 * HR / HTN, MBT / HTM), 256, HMMA_SMEM>>>(
        xh, BDIM, qkh, BDIM, nullptr, xq, xk, nullptr, HR, BDIM, 1.0f);
    // 3) E = exp(xq @ xk^T / 32) per (b,h) + quantized row sums   M=N=2048, K=64
    hmma_gemm<3><<<dim3(BT / HTN, BT / HTM, BB * BHEADS), 256, HMMA_SMEM>>>(
        xq, HR, xk, HR, part, e, nullptr, nullptr, BT, BRANK, 0.03125f);
    // 4) reduce partials -> 1/rowsum
    reduce_inv<<<(BB * BHEADS * BT) / 256, 256>>>(part, rinv);
    // 5) ctx = (E @ x) * rinv   M=65536 flat, N=1024, K=2048
    hmma_gemm<4><<<dim3(BDIM / HTN, (BB * BHEADS * BT) / HTM), 256, HMMA_SMEM>>>(
        e, BT, xt, BT, nullptr, ctx, nullptr, rinv, 0, BT, 1.0f);
    // 6) out = ctx @ VO   M=4096, N=1024, K=16384
    hmma_gemm<5><<<dim3(BDIM / HTN, MBT / HTM), 256, HMMA_SMEM>>>(
        ctx, HD, vot, HD, out, nullptr, nullptr, nullptr, BDIM, HD, 1.0f);
}